// round 14
// baseline (speedup 1.0000x reference)
#include <cuda_runtime.h>
#include <cuda_fp16.h>
#include <math.h>
#include <stdint.h>

#define Bb 64
#define Tt 512
#define Hh 768
#define Nn 2048
#define Pp 300
#define KP 320
#define BT (Bb*Tt)
#define BT2 (2*BT)

// ---------------- scratch (device globals; no allocation allowed) ----------
__device__ __half g_ent_h[(size_t)Nn*Hh],   g_ent_l[(size_t)Nn*Hh];
__device__ __half g_W1_h[Hh*Hh],            g_W1_l[Hh*Hh];
__device__ __half g_Wm_h[Pp*Hh],            g_Wm_l[Pp*Hh];
__device__ __half g_Wd_h[Pp*Hh],            g_Wd_l[Pp*Hh];
__device__ __half g_pool_h[(size_t)BT2*Hh];
__device__ __half g_pm_h[(size_t)BT2*KP];
__device__ __half g_pd_h[(size_t)Nn*KP],    g_pd_l[(size_t)Nn*KP];
__device__ float  g_part[(size_t)6*BT*3];   // logits partials per col-tile
__device__ float  g_sc[(size_t)BT2*Nn];
__device__ int    g_pred[BT];
__device__ int    g_rowinfo0[BT], g_rowinfo1[BT];
__device__ int    g_nvraw0[Bb],  g_nvraw1[Bb];
__device__ int    g_base0[Bb],   g_base1[Bb];
__device__ int    g_lsm_nv[2*Bb], g_lsm_base[2*Bb];
__device__ int    g_Rtot[4];                     // [0]=Rpad  [1]=R

// ---------------- helpers ----------------------------------------------------
__device__ __forceinline__ uint32_t smem_u32(const void* p){
    uint32_t a;
    asm("{ .reg .u64 t; cvta.to.shared.u64 t, %1; cvt.u32.u64 %0, t; }" : "=r"(a) : "l"(p));
    return a;
}
__device__ __forceinline__ void cp_async16(uint32_t dst, const void* src, bool ok){
    int sz = ok ? 16 : 0;   // src-size 0 -> zero-fill 16B
    asm volatile("cp.async.cg.shared.global [%0], [%1], 16, %2;" :: "r"(dst), "l"(src), "r"(sz));
}
__device__ __forceinline__ void cp_commit(){ asm volatile("cp.async.commit_group;" ::: "memory"); }
template<int N> __device__ __forceinline__ void cp_wait(){ asm volatile("cp.async.wait_group %0;" :: "n"(N) : "memory"); }

__device__ __forceinline__ void ldsm4(uint32_t* r, uint32_t addr){
    asm volatile("ldmatrix.sync.aligned.m8n8.x4.shared.b16 {%0,%1,%2,%3}, [%4];"
        : "=r"(r[0]), "=r"(r[1]), "=r"(r[2]), "=r"(r[3]) : "r"(addr));
}
__device__ __forceinline__ void mma16(float* d, const uint32_t* a, uint32_t b0, uint32_t b1){
    asm volatile(
        "mma.sync.aligned.m16n8k16.row.col.f32.f16.f16.f32 "
        "{%0,%1,%2,%3}, {%4,%5,%6,%7}, {%8,%9}, {%0,%1,%2,%3};"
        : "+f"(d[0]), "+f"(d[1]), "+f"(d[2]), "+f"(d[3])
        : "r"(a[0]), "r"(a[1]), "r"(a[2]), "r"(a[3]), "r"(b0), "r"(b1));
}
__device__ __forceinline__ void split16(float v, __half& h, __half& l){
    h = __float2half_rn(v);
    l = __float2half_rn(v - __half2float(h));
}

// ---------------- fp16 GEMM: C[M,N] = A[M,K] @ B[N,K]^T ----------------------
// CTA tile 128x128, BK=32, 8 warps (2m x 4n), warp tile 64x32, 3-stage cp.async,
// __launch_bounds__(256,2) -> <=128 regs -> 2 CTAs/SM.
// EP_LOGITS: fused relu(h)+W2 projection -> per-col-tile partials.
// CVT: A arrives as raw fp32 (gemm1); single-round in-stage conversion to
//      interleaved h/l planes (per-64-row groups: h at group*8192, l at +4096).
enum { EP_LOGITS = 0, EP_PAD = 1, EP_PLAIN = 2 };
#define ST_ALO 8192
#define ST_B   16384
#define ST_BLO 8192      // relative to ST_B
#define STAGE  32768
#define SMEM_GEMM (3*STAGE)              // 98304
#define SMEM_LOG  (3*STAGE + 6144 + 1536) // + psum[4][128][3] + w2s[3][128]
#define NTHR 256

template<int EPI, bool ROWMASK, int TERMS, bool CVT>
__global__ void __launch_bounds__(NTHR, 2) mma_gemm(
    const __half* __restrict__ Ah, const __half* __restrict__ Al,
    const float* __restrict__ Afp,
    const __half* __restrict__ Bh, const __half* __restrict__ Bl,
    float* __restrict__ C, __half* __restrict__ Ch, __half* __restrict__ Cl,
    int lda, int ldb, int ldc, int K, int Nreal, int NBreal,
    const float* __restrict__ bias, const int* __restrict__ rtot,
    const float* __restrict__ w2)
{
    extern __shared__ char smem[];
    const int m0 = blockIdx.y * 128, n0 = blockIdx.x * 128;
    const int tid = threadIdx.x;
    if (ROWMASK){
        if (m0 >= rtot[0]) return;     // beyond compacted rows
    }
    const uint32_t sb0 = smem_u32(smem);
    const int warp = tid >> 5, lane = tid & 31;
    const int wm = warp >> 2, wn = warp & 3;     // 2 x 4 warp grid, warp tile 64x32
    const int lr = lane >> 2, lc = lane & 3;

    float* psum = (float*)(smem + 3*STAGE);          // [4][128][3]
    float* w2s  = (float*)(smem + 3*STAGE + 6144);   // [3][128]
    if (EPI == EP_LOGITS && tid < 128){
        #pragma unroll
        for (int c = 0; c < 3; c++) w2s[c*128 + tid] = w2[c*Hh + n0 + tid];
    }

    float acc[4][4][4];
    #pragma unroll
    for (int i=0;i<4;i++)
        #pragma unroll
        for (int j=0;j<4;j++)
            #pragma unroll
            for (int q=0;q<4;q++) acc[i][j][q] = 0.f;

    const int arl = (lane & 7) + ((lane >> 3) & 1) * 8;
    const int acs = lane >> 4;
    const int nrl = (lane & 7) + (lane >> 4) * 8;
    const int bcs = (lane >> 3) & 1;
    uint32_t aoff[4], boff[2];
    #pragma unroll
    for (int mt = 0; mt < 4; mt++){
        int r = wm*64 + mt*16 + arl;
        int swz = acs ^ (r & 3) ^ ((r >> 2) & 1);
        if (CVT) aoff[mt] = (uint32_t)(((r >> 6) << 13) + ((r & 63) << 6) + (swz << 4));
        else     aoff[mt] = (uint32_t)((r << 6) + (swz << 4));
    }
    #pragma unroll
    for (int nb = 0; nb < 2; nb++){
        int r = wn*32 + nb*16 + nrl;
        boff[nb] = (uint32_t)ST_B + (uint32_t)((r << 6) + ((bcs ^ (r & 3) ^ ((r >> 2) & 1)) << 4));
    }
    const uint32_t ALO = CVT ? 4096u : (uint32_t)ST_ALO;

    auto load_tile = [&](int kt, int s){
        const int k0 = kt * 32;
        const uint32_t sbs = sb0 + (uint32_t)s * STAGE;
        if (CVT){
            #pragma unroll
            for (int j = 0; j < 8; j++){
                int idx = tid + j*NTHR;                 // 0..2047
                if (idx < 1024){                        // raw fp32 A: 128 rows x 8 float4
                    int row = idx >> 3, q = idx & 7;
                    uint32_t so = sbs + (uint32_t)(row*128 + q*16);
                    cp_async16(so, Afp + (size_t)(m0 + row)*lda + k0 + q*4, true);
                } else {                                // B planes: Bh, Bl
                    int b   = idx - 1024;
                    int pl  = b >> 9;
                    int rem = b & 511;
                    int row = rem >> 2, c = rem & 3;
                    int c2  = c ^ (row & 3) ^ ((row >> 2) & 1);
                    uint32_t so = sbs + (uint32_t)(ST_B + pl*ST_BLO + row*64 + c2*16);
                    bool ok = (n0 + row) < NBreal;
                    const __half* base = pl ? Bl : Bh;
                    const __half* src = ok ? (base + (size_t)(n0 + row)*ldb + k0 + c*8) : base;
                    cp_async16(so, src, ok);
                }
            }
        } else if (TERMS == 3){
            #pragma unroll
            for (int j = 0; j < 8; j++){
                int idx = tid + j*NTHR;
                if (idx < 1024){                        // A planes: Ah, Al
                    int pl  = idx >> 9;
                    int rem = idx & 511;
                    int row = rem >> 2, c = rem & 3;
                    int c2  = c ^ (row & 3) ^ ((row >> 2) & 1);
                    uint32_t so = sbs + (uint32_t)(pl*ST_ALO + row*64 + c2*16);
                    const __half* src = (pl ? Al : Ah) + (size_t)(m0 + row)*lda + k0 + c*8;
                    cp_async16(so, src, true);
                } else {
                    int b   = idx - 1024;
                    int pl  = b >> 9;
                    int rem = b & 511;
                    int row = rem >> 2, c = rem & 3;
                    int c2  = c ^ (row & 3) ^ ((row >> 2) & 1);
                    uint32_t so = sbs + (uint32_t)(ST_B + pl*ST_BLO + row*64 + c2*16);
                    bool ok = (n0 + row) < NBreal;
                    const __half* base = pl ? Bl : Bh;
                    const __half* src = ok ? (base + (size_t)(n0 + row)*ldb + k0 + c*8) : base;
                    cp_async16(so, src, ok);
                }
            }
        } else {   // TERMS == 2: planes Ah, Bh, Bl only
            #pragma unroll
            for (int j = 0; j < 6; j++){
                int idx = tid + j*NTHR;
                if (idx < 512){                          // Ah
                    int row = idx >> 2, c = idx & 3;
                    int c2  = c ^ (row & 3) ^ ((row >> 2) & 1);
                    uint32_t so = sbs + (uint32_t)(row*64 + c2*16);
                    cp_async16(so, Ah + (size_t)(m0 + row)*lda + k0 + c*8, true);
                } else {
                    int b   = idx - 512;
                    int pl  = b >> 9;
                    int rem = b & 511;
                    int row = rem >> 2, c = rem & 3;
                    int c2  = c ^ (row & 3) ^ ((row >> 2) & 1);
                    uint32_t so = sbs + (uint32_t)(ST_B + pl*ST_BLO + row*64 + c2*16);
                    bool ok = (n0 + row) < NBreal;
                    const __half* base = pl ? Bl : Bh;
                    const __half* src = ok ? (base + (size_t)(n0 + row)*ldb + k0 + c*8) : base;
                    cp_async16(so, src, ok);
                }
            }
        }
        cp_commit();
    };

    const int nkt = K >> 5;
    load_tile(0, 0);
    if (nkt > 1) load_tile(1, 1);
    for (int kt = 0; kt < nkt; kt++){
        const int s = kt % 3;
        if (kt + 1 < nkt) cp_wait<1>(); else cp_wait<0>();
        __syncthreads();

        if (CVT){
            // single-round in-stage fp32 -> interleaved h/l conversion
            char* sp = smem + s*STAGE;
            int r = tid >> 1, hh = tid & 1;     // row, 16-col half
            const float4* fp = (const float4*)(sp + r*128 + hh*64);
            float4 f0 = fp[0], f1 = fp[1], f2 = fp[2], f3 = fp[3];
            __syncthreads();
            float f[16] = {f0.x,f0.y,f0.z,f0.w, f1.x,f1.y,f1.z,f1.w,
                           f2.x,f2.y,f2.z,f2.w, f3.x,f3.y,f3.z,f3.w};
            __half hv[16], lv[16];
            #pragma unroll
            for (int j = 0; j < 16; j++) split16(f[j], hv[j], lv[j]);
            char* bp = sp + ((r >> 6) << 13) + ((r & 63) << 6);
            #pragma unroll
            for (int s2 = 0; s2 < 2; s2++){
                int seg = hh*2 + s2;
                int c2 = seg ^ (r & 3) ^ ((r >> 2) & 1);
                *(uint4*)(bp + (c2 << 4))        = *(uint4*)(hv + s2*8);
                *(uint4*)(bp + 4096 + (c2 << 4)) = *(uint4*)(lv + s2*8);
            }
            __syncthreads();
        }

        if (kt + 2 < nkt) load_tile(kt + 2, (kt + 2) % 3);
        const uint32_t sbs = sb0 + (uint32_t)s * STAGE;

        #pragma unroll
        for (int ks = 0; ks < 2; ks++){
            const uint32_t kx = (uint32_t)(ks << 5);
            uint32_t bhf[2][4], blf[2][4];
            #pragma unroll
            for (int nb = 0; nb < 2; nb++){
                uint32_t t = (sbs + boff[nb]) ^ kx;
                ldsm4(bhf[nb], t);
                ldsm4(blf[nb], t + ST_BLO);
            }
            #pragma unroll
            for (int mt = 0; mt < 4; mt++){
                uint32_t ahf[4], alf[4];
                uint32_t t = (sbs + aoff[mt]) ^ kx;
                ldsm4(ahf, t);
                if (TERMS == 3) ldsm4(alf, t + ALO);
                #pragma unroll
                for (int nt = 0; nt < 4; nt++){
                    const int nb = nt >> 1, p = (nt & 1) * 2;
                    float* d = acc[mt][nt];
                    mma16(d, ahf, bhf[nb][p], bhf[nb][p+1]);       // hi*hi
                    mma16(d, ahf, blf[nb][p], blf[nb][p+1]);       // hi*lo
                    if (TERMS == 3)
                        mma16(d, alf, bhf[nb][p], bhf[nb][p+1]);   // lo*hi
                }
            }
        }
    }

    if (EPI == EP_LOGITS){
        // fused: v = relu(acc + b1); partial[c] = sum_col v * W2[c][col]
        float w2v[4][2][3];
        float bv[4][2];
        #pragma unroll
        for (int nt = 0; nt < 4; nt++){
            int colL = wn*32 + nt*8 + lc*2;
            #pragma unroll
            for (int j = 0; j < 2; j++){
                bv[nt][j] = bias[n0 + colL + j];
                #pragma unroll
                for (int c = 0; c < 3; c++) w2v[nt][j][c] = w2s[c*128 + colL + j];
            }
        }
        #pragma unroll
        for (int mt = 0; mt < 4; mt++){
            float pA[3] = {0.f,0.f,0.f}, pB[3] = {0.f,0.f,0.f};
            #pragma unroll
            for (int nt = 0; nt < 4; nt++){
                float* a = acc[mt][nt];
                float v0 = a[0] + bv[nt][0]; v0 = v0 > 0.f ? v0 : 0.f;
                float v1 = a[1] + bv[nt][1]; v1 = v1 > 0.f ? v1 : 0.f;
                float v2 = a[2] + bv[nt][0]; v2 = v2 > 0.f ? v2 : 0.f;
                float v3 = a[3] + bv[nt][1]; v3 = v3 > 0.f ? v3 : 0.f;
                #pragma unroll
                for (int c = 0; c < 3; c++){
                    pA[c] += v0*w2v[nt][0][c] + v1*w2v[nt][1][c];
                    pB[c] += v2*w2v[nt][0][c] + v3*w2v[nt][1][c];
                }
            }
            #pragma unroll
            for (int off = 1; off <= 2; off <<= 1){
                #pragma unroll
                for (int c = 0; c < 3; c++){
                    pA[c] += __shfl_xor_sync(0xffffffffu, pA[c], off);
                    pB[c] += __shfl_xor_sync(0xffffffffu, pB[c], off);
                }
            }
            if (lc == 0){
                int rA = wm*64 + mt*16 + lr;
                #pragma unroll
                for (int c = 0; c < 3; c++){
                    psum[(wn*128 + rA)*3 + c]     = pA[c];
                    psum[(wn*128 + rA + 8)*3 + c] = pB[c];
                }
            }
        }
        __syncthreads();
        for (int r = tid; r < 128; r += NTHR){
            #pragma unroll
            for (int c = 0; c < 3; c++){
                float g = psum[(0*128 + r)*3 + c];
                g += psum[(1*128 + r)*3 + c];
                g += psum[(2*128 + r)*3 + c];
                g += psum[(3*128 + r)*3 + c];
                C[((size_t)blockIdx.x*BT + (m0 + r))*3 + c] = g;
            }
        }
        return;
    }

    // epilogue: registers -> gmem
    #pragma unroll
    for (int mt = 0; mt < 4; mt++){
        #pragma unroll
        for (int nt = 0; nt < 4; nt++){
            int row = m0 + wm*64 + mt*16 + lr;
            int col = n0 + wn*32 + nt*8 + lc*2;
            float* a = acc[mt][nt];
            if (EPI == EP_PLAIN){
                *(float2*)&C[(size_t)row*ldc + col]     = make_float2(a[0], a[1]);
                *(float2*)&C[(size_t)(row+8)*ldc + col] = make_float2(a[2], a[3]);
            } else { // EP_PAD: half hi (+lo if wanted), zero pad columns
                if (col + 2 <= ldc){
                    float v0 = (col   < Nreal) ? a[0] : 0.f;
                    float v1 = (col+1 < Nreal) ? a[1] : 0.f;
                    float v2 = (col   < Nreal) ? a[2] : 0.f;
                    float v3 = (col+1 < Nreal) ? a[3] : 0.f;
                    __half h0,l0,h1,l1,h2,l2,h3,l3;
                    split16(v0,h0,l0); split16(v1,h1,l1);
                    split16(v2,h2,l2); split16(v3,h3,l3);
                    *(__half2*)&Ch[(size_t)row*ldc + col]     = __halves2half2(h0, h1);
                    *(__half2*)&Ch[(size_t)(row+8)*ldc + col] = __halves2half2(h2, h3);
                    if (Cl){
                        *(__half2*)&Cl[(size_t)row*ldc + col]     = __halves2half2(l0, l1);
                        *(__half2*)&Cl[(size_t)(row+8)*ldc + col] = __halves2half2(l2, l3);
                    }
                }
            }
        }
    }
}

// ---------------- fused weight split: W1 | ent | Wm | Wd -----------------------
__global__ void __launch_bounds__(256) fsplit_kernel(
    const float* __restrict__ W1, const float* __restrict__ ent,
    const float* __restrict__ Wm, const float* __restrict__ Wd,
    __half* __restrict__ w1h, __half* __restrict__ w1l,
    __half* __restrict__ enth, __half* __restrict__ entl,
    __half* __restrict__ wmh, __half* __restrict__ wml,
    __half* __restrict__ wdh, __half* __restrict__ wdl)
{
    const int n1 = Hh*Hh, n2 = n1 + Nn*Hh, n3 = n2 + Pp*Hh, n4 = n3 + Pp*Hh;
    int i = blockIdx.x*256 + threadIdx.x;
    const float* src; __half *dh, *dl; int off;
    if (i < n1){ src = W1; dh = w1h; dl = w1l; off = i; }
    else if (i < n2){ src = ent; dh = enth; dl = entl; off = i - n1; }
    else if (i < n3){ src = Wm;  dh = wmh;  dl = wml;  off = i - n2; }
    else if (i < n4){ src = Wd;  dh = wdh;  dl = wdl;  off = i - n3; }
    else return;
    __half hv, lv; split16(src[off], hv, lv); dh[off] = hv; dl[off] = lv;
}

// ---------------- final 3-class head: sum partials + log_softmax + argmax -------
__global__ void __launch_bounds__(256) logits2_kernel(
    const float* __restrict__ gpart, const float* __restrict__ b2,
    float* __restrict__ out0, int* __restrict__ pred)
{
    int row = blockIdx.x*256 + threadIdx.x;
    float s[3];
    #pragma unroll
    for (int c = 0; c < 3; c++) s[c] = b2[c];
    #pragma unroll
    for (int k = 0; k < 6; k++)
        #pragma unroll
        for (int c = 0; c < 3; c++)
            s[c] += gpart[((size_t)k*BT + row)*3 + c];
    float m = fmaxf(s[0], fmaxf(s[1], s[2]));
    float lse = m + logf(expf(s[0]-m)+expf(s[1]-m)+expf(s[2]-m));
    size_t o = (size_t)row*3;
    out0[o+0] = s[0] - lse; out0[o+1] = s[1] - lse; out0[o+2] = s[2] - lse;
    int idx = 0; float best = s[0];
    if (s[1] > best){ best = s[1]; idx = 1; }
    if (s[2] > best){ idx = 2; }
    pred[row] = idx;
}

// ---------------- fused BIO scans (both passes) + compaction ---------------------
// One block, 32 warps; warp w scans (batch,pass) pairs w, w+32, w+64, w+96;
// thread 0 then runs the serial compaction after the block barrier.
__global__ void __launch_bounds__(1024) scancomb_kernel(
    const int* __restrict__ labels, const int* __restrict__ pred,
    int* __restrict__ ri0, int* __restrict__ nv0arr,
    int* __restrict__ ri1, int* __restrict__ nv1arr,
    int* __restrict__ base0, int* __restrict__ base1,
    int* __restrict__ lsm_nv, int* __restrict__ lsm_base, int* __restrict__ rtot)
{
    extern __shared__ int sh[];                 // 32 * 520 ints
    __shared__ int snv[128];
    int warp = threadIdx.x >> 5, lane = threadIdx.x & 31;
    int* pos = sh + warp*520;
    for (int p = warp; p < 128; p += 32){
        int pass = p >> 6, b = p & 63;
        const int* lab = (pass ? pred : labels) + b*Tt;
        int* rowinfo = pass ? ri1 : ri0;
        int base = 0;
        int first1 = Tt;
        int any2 = 0;
        #pragma unroll 1
        for (int c = 0; c < Tt/32; c++){
            int l = lab[c*32 + lane];
            unsigned m1 = __ballot_sync(0xffffffffu, l == 1);
            unsigned m2 = __ballot_sync(0xffffffffu, l == 2);
            if (l == 1) pos[base + __popc(m1 & ((1u<<lane)-1))] = c*32 + lane;
            if (first1 == Tt){
                if (m1){
                    int fl = __ffs(m1) - 1;
                    first1 = c*32 + fl;
                    any2 |= (m2 & ((1u<<fl)-1)) != 0;
                } else any2 |= (m2 != 0);
            }
            base += __popc(m1);
        }
        int m = base;
        int lead = any2;
        __syncwarp();
        if (lane == 0){
            pos[m] = Tt;
            if (lead) rowinfo[b*Tt] = (0<<16) | (m ? pos[0] : Tt);
            snv[p] = lead + m;
            (pass ? nv1arr : nv0arr)[b] = lead + m;
        }
        __syncwarp();
        for (int j = lane; j < m; j += 32){
            int s = pos[j], e = pos[j+1];
            rowinfo[b*Tt + lead + j] = (s<<16) | e;
        }
        __syncwarp();
    }
    __syncthreads();
    if (threadIdx.x == 0){
        int off = 0, cnt = 0;
        for (int b = 0; b < Bb; b++){
            int nv = snv[b];
            if (nv > 0){ base0[b] = off; lsm_base[cnt] = off; lsm_nv[cnt] = nv; cnt++; off += nv; }
            else base0[b] = -1;
        }
        for (int k = cnt; k < Bb; k++) lsm_nv[k] = 0;
        cnt = 0;
        for (int b = 0; b < Bb; b++){
            int nv = snv[Bb + b];
            if (nv > 0){ base1[b] = off; lsm_base[Bb+cnt] = off; lsm_nv[Bb+cnt] = nv; cnt++; off += nv; }
            else base1[b] = -1;
        }
        for (int k = cnt; k < Bb; k++) lsm_nv[Bb+k] = 0;
        rtot[1] = off;
        rtot[0] = (off + 127) & ~127;
    }
}

// ---------------- zero pooled pad rows [R, Rpad) (hi plane only) -----------------
__global__ void __launch_bounds__(256) padzero_kernel(
    const int* __restrict__ rtot, __half* __restrict__ ph)
{
    int row = rtot[1] + blockIdx.x;
    if (row >= rtot[0]) return;
    size_t off = (size_t)row*Hh;
    __half z = __float2half(0.f);
    for (int i = threadIdx.x; i < Hh; i += 256) ph[off+i] = z;
}

// ---------------- segment means -> globally compacted pooled rows (hi only) -----
// grid (Bb, 16, 2); z selects pass (labels vs pred)
__global__ void __launch_bounds__(256) pool2_kernel(
    const int* __restrict__ labels, const int* __restrict__ pred,
    const float* __restrict__ hidden,
    const int* __restrict__ ri0, const int* __restrict__ nv0arr, const int* __restrict__ b0arr,
    const int* __restrict__ ri1, const int* __restrict__ nv1arr, const int* __restrict__ b1arr,
    __half* __restrict__ ph)
{
    int b = blockIdx.x;
    int z = blockIdx.z;
    const int* lsrc   = (z ? pred : labels);
    const int* rowinfo = z ? ri1 : ri0;
    int d  = (z ? b1arr : b0arr)[b];
    if (d < 0) return;
    int nv = (z ? nv1arr : nv0arr)[b];
    __shared__ int labs[Tt];
    int tid = threadIdx.x;
    for (int i=tid;i<Tt;i+=256) labs[i] = lsrc[b*Tt+i];
    __syncthreads();
    int r0 = blockIdx.y * 32;
    int r1 = min(r0+32, nv);
    for (int r=r0; r<r1; r++){
        int info = rowinfo[b*Tt + r];
        int s = info >> 16, e = info & 0xffff;
        float a0=0.f,a1=0.f,a2=0.f;
        int cnt = 0;
        for (int t=s;t<e;t++){
            if (labs[t] != 0){
                cnt++;
                const float* hp = hidden + ((size_t)(b*Tt)+t)*Hh;
                a0 += hp[tid]; a1 += hp[tid+256]; a2 += hp[tid+512];
            }
        }
        float inv = 1.0f / (float)cnt;
        size_t off = ((size_t)(d + r))*Hh;
        ph[off+tid]     = __float2half_rn(a0*inv);
        ph[off+tid+256] = __float2half_rn(a1*inv);
        ph[off+tid+512] = __float2half_rn(a2*inv);
    }
}

// ---------------- row log-softmax over compacted sc ------------------------------
__global__ void __launch_bounds__(256) lsm_kernel(
    const float* __restrict__ sc, const int* __restrict__ lsm_nv,
    const int* __restrict__ lsm_base, float* __restrict__ out1, float* __restrict__ out2)
{
    int row = blockIdx.x*8 + (threadIdx.x >> 5);
    int p   = blockIdx.y;
    int lane = threadIdx.x & 31;
    int bb = row >> 9, t = row & 511;
    int nv = lsm_nv[p*Bb + bb];
    float* op = (p ? out2 : out1) + (size_t)row*Nn;
    if (t >= nv){
        const float CNEG = -7.6246189861593985f;   // -log(2048)
        float4 c4 = make_float4(CNEG,CNEG,CNEG,CNEG);
        for (int i=lane;i<Nn/4;i+=32) __stcs((float4*)op + i, c4);
        return;
    }
    int srow = lsm_base[p*Bb + bb] + t;
    const float4* ip = (const float4*)(sc + (size_t)srow*Nn);
    float4 v[16];
    float m = -3.4e38f;
    #pragma unroll
    for (int i=0;i<16;i++){
        v[i] = ip[lane + i*32];
        m = fmaxf(m, fmaxf(fmaxf(v[i].x,v[i].y), fmaxf(v[i].z,v[i].w)));
    }
    #pragma unroll
    for (int off=16;off;off>>=1) m = fmaxf(m, __shfl_xor_sync(0xffffffffu, m, off));
    float s = 0.f;
    #pragma unroll
    for (int i=0;i<16;i++)
        s += expf(v[i].x-m)+expf(v[i].y-m)+expf(v[i].z-m)+expf(v[i].w-m);
    #pragma unroll
    for (int off=16;off;off>>=1) s += __shfl_xor_sync(0xffffffffu, s, off);
    float corr = m + logf(s);
    #pragma unroll
    for (int i=0;i<16;i++){
        float4 o = v[i];
        o.x-=corr; o.y-=corr; o.z-=corr; o.w-=corr;
        __stcs((float4*)op + lane + i*32, o);
    }
}

// ---------------- host -------------------------------------------------------------
extern "C" void kernel_launch(void* const* d_in, const int* in_sizes, int n_in,
                              void* d_out, int out_size)
{
    (void)in_sizes; (void)n_in; (void)out_size;
    const int*   labels = (const int*)  d_in[0];
    const float* hidden = (const float*)d_in[1];
    const float* ent    = (const float*)d_in[2];
    const float* W1     = (const float*)d_in[3];
    const float* b1     = (const float*)d_in[4];
    const float* W2     = (const float*)d_in[5];
    const float* b2     = (const float*)d_in[6];
    const float* Wm     = (const float*)d_in[7];
    const float* Wd     = (const float*)d_in[8];

    float* out0 = (float*)d_out;
    float* s1o  = out0 + (size_t)BT*3;
    float* s2o  = s1o  + (size_t)BT*Nn;

    __half *enth,*entl,*w1h,*w1l,*wmh,*wml,*wdh,*wdl;
    __half *poolh,*pmh,*pdh,*pdl;
    float *gpart, *sc;
    int *pred, *ri0, *ri1, *nv0, *nv1, *b0, *b1a, *lnv, *lbs, *rtot;
    cudaGetSymbolAddress((void**)&enth, g_ent_h);  cudaGetSymbolAddress((void**)&entl, g_ent_l);
    cudaGetSymbolAddress((void**)&w1h,  g_W1_h);   cudaGetSymbolAddress((void**)&w1l,  g_W1_l);
    cudaGetSymbolAddress((void**)&wmh,  g_Wm_h);   cudaGetSymbolAddress((void**)&wml,  g_Wm_l);
    cudaGetSymbolAddress((void**)&wdh,  g_Wd_h);   cudaGetSymbolAddress((void**)&wdl,  g_Wd_l);
    cudaGetSymbolAddress((void**)&poolh,g_pool_h);
    cudaGetSymbolAddress((void**)&pmh,  g_pm_h);
    cudaGetSymbolAddress((void**)&pdh,  g_pd_h);   cudaGetSymbolAddress((void**)&pdl,  g_pd_l);
    cudaGetSymbolAddress((void**)&gpart,g_part);
    cudaGetSymbolAddress((void**)&sc,   g_sc);
    cudaGetSymbolAddress((void**)&pred, g_pred);
    cudaGetSymbolAddress((void**)&ri0,  g_rowinfo0);
    cudaGetSymbolAddress((void**)&ri1,  g_rowinfo1);
    cudaGetSymbolAddress((void**)&nv0,  g_nvraw0);
    cudaGetSymbolAddress((void**)&nv1,  g_nvraw1);
    cudaGetSymbolAddress((void**)&b0,   g_base0);
    cudaGetSymbolAddress((void**)&b1a,  g_base1);
    cudaGetSymbolAddress((void**)&lnv,  g_lsm_nv);
    cudaGetSymbolAddress((void**)&lbs,  g_lsm_base);
    cudaGetSymbolAddress((void**)&rtot, g_Rtot);

    cudaFuncSetAttribute((const void*)mma_gemm<EP_LOGITS,false,3,true>, cudaFuncAttributeMaxDynamicSharedMemorySize, SMEM_LOG);
    cudaFuncSetAttribute((const void*)mma_gemm<EP_PAD,false,2,false>,   cudaFuncAttributeMaxDynamicSharedMemorySize, SMEM_GEMM);
    cudaFuncSetAttribute((const void*)mma_gemm<EP_PAD,true,2,false>,    cudaFuncAttributeMaxDynamicSharedMemorySize, SMEM_GEMM);
    cudaFuncSetAttribute((const void*)mma_gemm<EP_PLAIN,true,2,false>,  cudaFuncAttributeMaxDynamicSharedMemorySize, SMEM_GEMM);
    cudaFuncSetAttribute((const void*)scancomb_kernel, cudaFuncAttributeMaxDynamicSharedMemorySize, 32*520*4);

    const int NSPLIT = Hh*Hh + Nn*Hh + 2*Pp*Hh;

    // 1) fused weight splits (one launch)
    fsplit_kernel<<<(NSPLIT+255)/256, 256>>>(W1, ent, Wm, Wd,
        w1h, w1l, enth, entl, wmh, wml, wdh, wdl);

    // 2) fused gemm1: h = relu(x@W1^T+b1) in-flight (fp32 A converted in-stage);
    //    gpart[cb] = h_block @ W2^T  (h never materialized)
    mma_gemm<EP_LOGITS,false,3,true><<<dim3(Hh/128, BT/128), NTHR, SMEM_LOG>>>(
        nullptr, nullptr, hidden, w1h, w1l, gpart, nullptr, nullptr,
        Hh, Hh, 3, Hh, Hh, Hh, b1, nullptr, W2);

    // 3) bio logits -> out0 + predicted labels
    logits2_kernel<<<BT/256, 256>>>(gpart, b2, out0, pred);

    // 4) pd = ent @ Wd^T -> half hi/lo planes, K-padded to KP (2-term)
    mma_gemm<EP_PAD,false,2,false><<<dim3(3, Nn/128), NTHR, SMEM_GEMM>>>(
        enth, entl, nullptr, wdh, wdl, nullptr, pdh, pdl,
        Hh, Hh, KP, Hh, Pp, Pp, nullptr, nullptr, nullptr);

    // 5) fused scans + compaction (one launch), pools (one launch), pad-zero
    scancomb_kernel<<<1, 1024, 32*520*4>>>(labels, pred, ri0, nv0, ri1, nv1,
        b0, b1a, lnv, lbs, rtot);
    pool2_kernel<<<dim3(Bb, 16, 2), 256>>>(labels, pred, hidden,
        ri0, nv0, b0, ri1, nv1, b1a, poolh);
    padzero_kernel<<<128, 256>>>(rtot, poolh);

    // 6) pm = pooled @ Wm^T over compacted rows — 2-term, hi-plane output only
    mma_gemm<EP_PAD,true,2,false><<<dim3(3, BT2/128), NTHR, SMEM_GEMM>>>(
        poolh, nullptr, nullptr, wmh, wml, nullptr, pmh, nullptr,
        Hh, Hh, KP, Hh, Pp, Pp, nullptr, rtot, nullptr);

    // 7) sc = pm @ pd^T over compacted rows — 2-term
    mma_gemm<EP_PLAIN,true,2,false><<<dim3(Nn/128, BT2/128), NTHR, SMEM_GEMM>>>(
        pmh, nullptr, nullptr, pdh, pdl, sc, nullptr, nullptr,
        KP, KP, Nn, KP, Nn, Nn, nullptr, rtot, nullptr);

    // 8) log-softmax scatter to both outputs
    lsm_kernel<<<dim3(BT/8, 2), 256>>>(sc, lnv, lbs, s1o, s2o);
}

// round 15
// speedup vs baseline: 1.0578x; 1.0578x over previous
#include <cuda_runtime.h>
#include <cuda_fp16.h>
#include <math.h>
#include <stdint.h>

#define Bb 64
#define Tt 512
#define Hh 768
#define Nn 2048
#define Pp 300
#define KP 320
#define BT (Bb*Tt)
#define BT2 (2*BT)

// ---------------- scratch (device globals; no allocation allowed) ----------
__device__ __half g_ent_h[(size_t)Nn*Hh],   g_ent_l[(size_t)Nn*Hh];
__device__ __half g_W1_h[Hh*Hh],            g_W1_l[Hh*Hh];
__device__ __half g_Wm_h[Pp*Hh],            g_Wm_l[Pp*Hh];
__device__ __half g_Wd_h[Pp*Hh],            g_Wd_l[Pp*Hh];
__device__ __half g_pool_h[(size_t)BT2*Hh];
__device__ __half g_pm_h[(size_t)BT2*KP];
__device__ __half g_pd_h[(size_t)Nn*KP],    g_pd_l[(size_t)Nn*KP];
__device__ float  g_part[(size_t)6*BT*3];   // logits partials per col-tile
__device__ float  g_sc[(size_t)BT2*Nn];
__device__ int    g_pred[BT];
__device__ int    g_rowinfo0[BT], g_rowinfo1[BT];
__device__ int    g_nvraw0[Bb],  g_nvraw1[Bb];
__device__ int    g_base0[Bb],   g_base1[Bb];
__device__ int    g_lsm_nv[2*Bb], g_lsm_base[2*Bb];
__device__ int    g_Rtot[4];                     // [0]=Rpad  [1]=R

// ---------------- helpers ----------------------------------------------------
__device__ __forceinline__ uint32_t smem_u32(const void* p){
    uint32_t a;
    asm("{ .reg .u64 t; cvta.to.shared.u64 t, %1; cvt.u32.u64 %0, t; }" : "=r"(a) : "l"(p));
    return a;
}
__device__ __forceinline__ void cp_async16(uint32_t dst, const void* src, bool ok){
    int sz = ok ? 16 : 0;   // src-size 0 -> zero-fill 16B
    asm volatile("cp.async.cg.shared.global [%0], [%1], 16, %2;" :: "r"(dst), "l"(src), "r"(sz));
}
__device__ __forceinline__ void cp_commit(){ asm volatile("cp.async.commit_group;" ::: "memory"); }
template<int N> __device__ __forceinline__ void cp_wait(){ asm volatile("cp.async.wait_group %0;" :: "n"(N) : "memory"); }

__device__ __forceinline__ void ldsm4(uint32_t* r, uint32_t addr){
    asm volatile("ldmatrix.sync.aligned.m8n8.x4.shared.b16 {%0,%1,%2,%3}, [%4];"
        : "=r"(r[0]), "=r"(r[1]), "=r"(r[2]), "=r"(r[3]) : "r"(addr));
}
__device__ __forceinline__ void mma16(float* d, const uint32_t* a, uint32_t b0, uint32_t b1){
    asm volatile(
        "mma.sync.aligned.m16n8k16.row.col.f32.f16.f16.f32 "
        "{%0,%1,%2,%3}, {%4,%5,%6,%7}, {%8,%9}, {%0,%1,%2,%3};"
        : "+f"(d[0]), "+f"(d[1]), "+f"(d[2]), "+f"(d[3])
        : "r"(a[0]), "r"(a[1]), "r"(a[2]), "r"(a[3]), "r"(b0), "r"(b1));
}
__device__ __forceinline__ void split16(float v, __half& h, __half& l){
    h = __float2half_rn(v);
    l = __float2half_rn(v - __half2float(h));
}

// ---------------- fp16 GEMM: C[M,N] = A[M,K] @ B[N,K]^T ----------------------
// CTA tile 128x128, BK=32, 8 warps (2m x 4n), warp tile 64x32, 3-stage cp.async,
// __launch_bounds__(256,2) -> <=128 regs -> 2 CTAs/SM.
// EP_LOGITS: fused relu(h)+W2 projection -> per-col-tile partials.
// CVT: A arrives as raw fp32 (gemm1); 2-round in-stage conversion to
//      interleaved h/l planes (per-64-row groups: h at group*8192, l at +4096).
enum { EP_LOGITS = 0, EP_PAD = 1, EP_PLAIN = 2 };
#define ST_ALO 8192
#define ST_B   16384
#define ST_BLO 8192      // relative to ST_B
#define STAGE  32768
#define SMEM_GEMM (3*STAGE)              // 98304
#define SMEM_LOG  (3*STAGE + 6144 + 1536) // + psum[4][128][3] + w2s[3][128]
#define NTHR 256

template<int EPI, bool ROWMASK, int TERMS, bool CVT>
__global__ void __launch_bounds__(NTHR, 2) mma_gemm(
    const __half* __restrict__ Ah, const __half* __restrict__ Al,
    const float* __restrict__ Afp,
    const __half* __restrict__ Bh, const __half* __restrict__ Bl,
    float* __restrict__ C, __half* __restrict__ Ch, __half* __restrict__ Cl,
    int lda, int ldb, int ldc, int K, int Nreal, int NBreal,
    const float* __restrict__ bias, const int* __restrict__ rtot,
    const float* __restrict__ w2)
{
    extern __shared__ char smem[];
    const int m0 = blockIdx.y * 128, n0 = blockIdx.x * 128;
    const int tid = threadIdx.x;
    if (ROWMASK){
        if (m0 >= rtot[0]) return;     // beyond compacted rows
    }
    const uint32_t sb0 = smem_u32(smem);
    const int warp = tid >> 5, lane = tid & 31;
    const int wm = warp >> 2, wn = warp & 3;     // 2 x 4 warp grid, warp tile 64x32
    const int lr = lane >> 2, lc = lane & 3;

    float* psum = (float*)(smem + 3*STAGE);          // [4][128][3]
    float* w2s  = (float*)(smem + 3*STAGE + 6144);   // [3][128]
    if (EPI == EP_LOGITS && tid < 128){
        #pragma unroll
        for (int c = 0; c < 3; c++) w2s[c*128 + tid] = w2[c*Hh + n0 + tid];
    }

    float acc[4][4][4];
    #pragma unroll
    for (int i=0;i<4;i++)
        #pragma unroll
        for (int j=0;j<4;j++)
            #pragma unroll
            for (int q=0;q<4;q++) acc[i][j][q] = 0.f;

    const int arl = (lane & 7) + ((lane >> 3) & 1) * 8;
    const int acs = lane >> 4;
    const int nrl = (lane & 7) + (lane >> 4) * 8;
    const int bcs = (lane >> 3) & 1;
    uint32_t aoff[4], boff[2];
    #pragma unroll
    for (int mt = 0; mt < 4; mt++){
        int r = wm*64 + mt*16 + arl;
        int swz = acs ^ (r & 3) ^ ((r >> 2) & 1);
        if (CVT) aoff[mt] = (uint32_t)(((r >> 6) << 13) + ((r & 63) << 6) + (swz << 4));
        else     aoff[mt] = (uint32_t)((r << 6) + (swz << 4));
    }
    #pragma unroll
    for (int nb = 0; nb < 2; nb++){
        int r = wn*32 + nb*16 + nrl;
        boff[nb] = (uint32_t)ST_B + (uint32_t)((r << 6) + ((bcs ^ (r & 3) ^ ((r >> 2) & 1)) << 4));
    }
    const uint32_t ALO = CVT ? 4096u : (uint32_t)ST_ALO;

    auto load_tile = [&](int kt, int s){
        const int k0 = kt * 32;
        const uint32_t sbs = sb0 + (uint32_t)s * STAGE;
        if (CVT){
            #pragma unroll
            for (int j = 0; j < 8; j++){
                int idx = tid + j*NTHR;                 // 0..2047
                if (idx < 1024){                        // raw fp32 A: 128 rows x 8 float4
                    int row = idx >> 3, q = idx & 7;
                    uint32_t so = sbs + (uint32_t)(row*128 + q*16);
                    cp_async16(so, Afp + (size_t)(m0 + row)*lda + k0 + q*4, true);
                } else {                                // B planes: Bh, Bl
                    int b   = idx - 1024;
                    int pl  = b >> 9;
                    int rem = b & 511;
                    int row = rem >> 2, c = rem & 3;
                    int c2  = c ^ (row & 3) ^ ((row >> 2) & 1);
                    uint32_t so = sbs + (uint32_t)(ST_B + pl*ST_BLO + row*64 + c2*16);
                    bool ok = (n0 + row) < NBreal;
                    const __half* base = pl ? Bl : Bh;
                    const __half* src = ok ? (base + (size_t)(n0 + row)*ldb + k0 + c*8) : base;
                    cp_async16(so, src, ok);
                }
            }
        } else if (TERMS == 3){
            #pragma unroll
            for (int j = 0; j < 8; j++){
                int idx = tid + j*NTHR;
                if (idx < 1024){                        // A planes: Ah, Al
                    int pl  = idx >> 9;
                    int rem = idx & 511;
                    int row = rem >> 2, c = rem & 3;
                    int c2  = c ^ (row & 3) ^ ((row >> 2) & 1);
                    uint32_t so = sbs + (uint32_t)(pl*ST_ALO + row*64 + c2*16);
                    const __half* src = (pl ? Al : Ah) + (size_t)(m0 + row)*lda + k0 + c*8;
                    cp_async16(so, src, true);
                } else {
                    int b   = idx - 1024;
                    int pl  = b >> 9;
                    int rem = b & 511;
                    int row = rem >> 2, c = rem & 3;
                    int c2  = c ^ (row & 3) ^ ((row >> 2) & 1);
                    uint32_t so = sbs + (uint32_t)(ST_B + pl*ST_BLO + row*64 + c2*16);
                    bool ok = (n0 + row) < NBreal;
                    const __half* base = pl ? Bl : Bh;
                    const __half* src = ok ? (base + (size_t)(n0 + row)*ldb + k0 + c*8) : base;
                    cp_async16(so, src, ok);
                }
            }
        } else {   // TERMS == 2: planes Ah, Bh, Bl only
            #pragma unroll
            for (int j = 0; j < 6; j++){
                int idx = tid + j*NTHR;
                if (idx < 512){                          // Ah
                    int row = idx >> 2, c = idx & 3;
                    int c2  = c ^ (row & 3) ^ ((row >> 2) & 1);
                    uint32_t so = sbs + (uint32_t)(row*64 + c2*16);
                    cp_async16(so, Ah + (size_t)(m0 + row)*lda + k0 + c*8, true);
                } else {
                    int b   = idx - 512;
                    int pl  = b >> 9;
                    int rem = b & 511;
                    int row = rem >> 2, c = rem & 3;
                    int c2  = c ^ (row & 3) ^ ((row >> 2) & 1);
                    uint32_t so = sbs + (uint32_t)(ST_B + pl*ST_BLO + row*64 + c2*16);
                    bool ok = (n0 + row) < NBreal;
                    const __half* base = pl ? Bl : Bh;
                    const __half* src = ok ? (base + (size_t)(n0 + row)*ldb + k0 + c*8) : base;
                    cp_async16(so, src, ok);
                }
            }
        }
        cp_commit();
    };

    const int nkt = K >> 5;
    load_tile(0, 0);
    if (nkt > 1) load_tile(1, 1);
    for (int kt = 0; kt < nkt; kt++){
        const int s = kt % 3;
        if (kt + 1 < nkt) cp_wait<1>(); else cp_wait<0>();
        __syncthreads();

        if (CVT){
            // in-stage fp32 -> interleaved h/l conversion, 2 row-group rounds
            char* sp = smem + s*STAGE;
            #pragma unroll
            for (int rnd = 0; rnd < 2; rnd++){
                int r   = rnd*64 + (tid >> 2);
                int seg = tid & 3;
                const float4* fp = (const float4*)(sp + (r & 63)*128 + (r >> 6)*8192 + seg*32);
                float4 f0 = fp[0], f1 = fp[1];
                __syncthreads();
                float f[8] = {f0.x,f0.y,f0.z,f0.w,f1.x,f1.y,f1.z,f1.w};
                __half hv[8], lv[8];
                #pragma unroll
                for (int j = 0; j < 8; j++) split16(f[j], hv[j], lv[j]);
                int c2 = seg ^ (r & 3) ^ ((r >> 2) & 1);
                char* hp = sp + ((r >> 6) << 13) + ((r & 63) << 6) + (c2 << 4);
                *(uint4*)hp          = *(uint4*)hv;
                *(uint4*)(hp + 4096) = *(uint4*)lv;
                __syncthreads();
            }
        }

        if (kt + 2 < nkt) load_tile(kt + 2, (kt + 2) % 3);
        const uint32_t sbs = sb0 + (uint32_t)s * STAGE;

        #pragma unroll
        for (int ks = 0; ks < 2; ks++){
            const uint32_t kx = (uint32_t)(ks << 5);
            uint32_t bhf[2][4], blf[2][4];
            #pragma unroll
            for (int nb = 0; nb < 2; nb++){
                uint32_t t = (sbs + boff[nb]) ^ kx;
                ldsm4(bhf[nb], t);
                ldsm4(blf[nb], t + ST_BLO);
            }
            #pragma unroll
            for (int mt = 0; mt < 4; mt++){
                uint32_t ahf[4], alf[4];
                uint32_t t = (sbs + aoff[mt]) ^ kx;
                ldsm4(ahf, t);
                if (TERMS == 3) ldsm4(alf, t + ALO);
                #pragma unroll
                for (int nt = 0; nt < 4; nt++){
                    const int nb = nt >> 1, p = (nt & 1) * 2;
                    float* d = acc[mt][nt];
                    mma16(d, ahf, bhf[nb][p], bhf[nb][p+1]);       // hi*hi
                    mma16(d, ahf, blf[nb][p], blf[nb][p+1]);       // hi*lo
                    if (TERMS == 3)
                        mma16(d, alf, bhf[nb][p], bhf[nb][p+1]);   // lo*hi
                }
            }
        }
        if (CVT) __syncthreads();   // stage s fully consumed before reuse as fp32 target
    }

    if (EPI == EP_LOGITS){
        // fused: v = relu(acc + b1); partial[c] = sum_col v * W2[c][col]
        float w2v[4][2][3];
        float bv[4][2];
        #pragma unroll
        for (int nt = 0; nt < 4; nt++){
            int colL = wn*32 + nt*8 + lc*2;
            #pragma unroll
            for (int j = 0; j < 2; j++){
                bv[nt][j] = bias[n0 + colL + j];
                #pragma unroll
                for (int c = 0; c < 3; c++) w2v[nt][j][c] = w2s[c*128 + colL + j];
            }
        }
        #pragma unroll
        for (int mt = 0; mt < 4; mt++){
            float pA[3] = {0.f,0.f,0.f}, pB[3] = {0.f,0.f,0.f};
            #pragma unroll
            for (int nt = 0; nt < 4; nt++){
                float* a = acc[mt][nt];
                float v0 = a[0] + bv[nt][0]; v0 = v0 > 0.f ? v0 : 0.f;
                float v1 = a[1] + bv[nt][1]; v1 = v1 > 0.f ? v1 : 0.f;
                float v2 = a[2] + bv[nt][0]; v2 = v2 > 0.f ? v2 : 0.f;
                float v3 = a[3] + bv[nt][1]; v3 = v3 > 0.f ? v3 : 0.f;
                #pragma unroll
                for (int c = 0; c < 3; c++){
                    pA[c] += v0*w2v[nt][0][c] + v1*w2v[nt][1][c];
                    pB[c] += v2*w2v[nt][0][c] + v3*w2v[nt][1][c];
                }
            }
            #pragma unroll
            for (int off = 1; off <= 2; off <<= 1){
                #pragma unroll
                for (int c = 0; c < 3; c++){
                    pA[c] += __shfl_xor_sync(0xffffffffu, pA[c], off);
                    pB[c] += __shfl_xor_sync(0xffffffffu, pB[c], off);
                }
            }
            if (lc == 0){
                int rA = wm*64 + mt*16 + lr;
                #pragma unroll
                for (int c = 0; c < 3; c++){
                    psum[(wn*128 + rA)*3 + c]     = pA[c];
                    psum[(wn*128 + rA + 8)*3 + c] = pB[c];
                }
            }
        }
        __syncthreads();
        for (int r = tid; r < 128; r += NTHR){
            #pragma unroll
            for (int c = 0; c < 3; c++){
                float g = psum[(0*128 + r)*3 + c];
                g += psum[(1*128 + r)*3 + c];
                g += psum[(2*128 + r)*3 + c];
                g += psum[(3*128 + r)*3 + c];
                C[((size_t)blockIdx.x*BT + (m0 + r))*3 + c] = g;
            }
        }
        return;
    }

    // epilogue: registers -> gmem
    #pragma unroll
    for (int mt = 0; mt < 4; mt++){
        #pragma unroll
        for (int nt = 0; nt < 4; nt++){
            int row = m0 + wm*64 + mt*16 + lr;
            int col = n0 + wn*32 + nt*8 + lc*2;
            float* a = acc[mt][nt];
            if (EPI == EP_PLAIN){
                *(float2*)&C[(size_t)row*ldc + col]     = make_float2(a[0], a[1]);
                *(float2*)&C[(size_t)(row+8)*ldc + col] = make_float2(a[2], a[3]);
            } else { // EP_PAD: half hi (+lo if provided), zero pad columns
                if (col + 2 <= ldc){
                    float v0 = (col   < Nreal) ? a[0] : 0.f;
                    float v1 = (col+1 < Nreal) ? a[1] : 0.f;
                    float v2 = (col   < Nreal) ? a[2] : 0.f;
                    float v3 = (col+1 < Nreal) ? a[3] : 0.f;
                    __half h0,l0,h1,l1,h2,l2,h3,l3;
                    split16(v0,h0,l0); split16(v1,h1,l1);
                    split16(v2,h2,l2); split16(v3,h3,l3);
                    *(__half2*)&Ch[(size_t)row*ldc + col]     = __halves2half2(h0, h1);
                    *(__half2*)&Ch[(size_t)(row+8)*ldc + col] = __halves2half2(h2, h3);
                    if (Cl){
                        *(__half2*)&Cl[(size_t)row*ldc + col]     = __halves2half2(l0, l1);
                        *(__half2*)&Cl[(size_t)(row+8)*ldc + col] = __halves2half2(l2, l3);
                    }
                }
            }
        }
    }
}

// ---------------- fused weight split: W1 | ent | Wm | Wd -----------------------
__global__ void __launch_bounds__(256) fsplit_kernel(
    const float* __restrict__ W1, const float* __restrict__ ent,
    const float* __restrict__ Wm, const float* __restrict__ Wd,
    __half* __restrict__ w1h, __half* __restrict__ w1l,
    __half* __restrict__ enth, __half* __restrict__ entl,
    __half* __restrict__ wmh, __half* __restrict__ wml,
    __half* __restrict__ wdh, __half* __restrict__ wdl)
{
    const int n1 = Hh*Hh, n2 = n1 + Nn*Hh, n3 = n2 + Pp*Hh, n4 = n3 + Pp*Hh;
    int i = blockIdx.x*256 + threadIdx.x;
    const float* src; __half *dh, *dl; int off;
    if (i < n1){ src = W1; dh = w1h; dl = w1l; off = i; }
    else if (i < n2){ src = ent; dh = enth; dl = entl; off = i - n1; }
    else if (i < n3){ src = Wm;  dh = wmh;  dl = wml;  off = i - n2; }
    else if (i < n4){ src = Wd;  dh = wdh;  dl = wdl;  off = i - n3; }
    else return;
    __half hv, lv; split16(src[off], hv, lv); dh[off] = hv; dl[off] = lv;
}

// ---------------- final 3-class head: sum partials + log_softmax + argmax -------
__global__ void __launch_bounds__(256) logits2_kernel(
    const float* __restrict__ gpart, const float* __restrict__ b2,
    float* __restrict__ out0, int* __restrict__ pred)
{
    int row = blockIdx.x*256 + threadIdx.x;
    float s[3];
    #pragma unroll
    for (int c = 0; c < 3; c++) s[c] = b2[c];
    #pragma unroll
    for (int k = 0; k < 6; k++)
        #pragma unroll
        for (int c = 0; c < 3; c++)
            s[c] += gpart[((size_t)k*BT + row)*3 + c];
    float m = fmaxf(s[0], fmaxf(s[1], s[2]));
    float lse = m + logf(expf(s[0]-m)+expf(s[1]-m)+expf(s[2]-m));
    size_t o = (size_t)row*3;
    out0[o+0] = s[0] - lse; out0[o+1] = s[1] - lse; out0[o+2] = s[2] - lse;
    int idx = 0; float best = s[0];
    if (s[1] > best){ best = s[1]; idx = 1; }
    if (s[2] > best){ idx = 2; }
    pred[row] = idx;
}

// ---------------- BIO segment scan, both passes (grid.y selects source) ---------
__global__ void scan2_kernel(const int* __restrict__ labels, const int* __restrict__ pred,
                             int* __restrict__ ri0, int* __restrict__ nv0,
                             int* __restrict__ ri1, int* __restrict__ nv1)
{
    __shared__ int pos[513];
    int b = blockIdx.x, lane = threadIdx.x;
    const int* lab = (blockIdx.y ? pred : labels) + b*Tt;
    int* rowinfo = blockIdx.y ? ri1 : ri0;
    int* nvraw   = blockIdx.y ? nv1 : nv0;
    int base = 0;
    int first1 = Tt;
    int any2 = 0;
    #pragma unroll 1
    for (int c = 0; c < Tt/32; c++){
        int l = lab[c*32 + lane];
        unsigned m1 = __ballot_sync(0xffffffffu, l == 1);
        unsigned m2 = __ballot_sync(0xffffffffu, l == 2);
        if (l == 1) pos[base + __popc(m1 & ((1u<<lane)-1))] = c*32 + lane;
        if (first1 == Tt){
            if (m1){
                int fl = __ffs(m1) - 1;
                first1 = c*32 + fl;
                any2 |= (m2 & ((1u<<fl)-1)) != 0;
            } else any2 |= (m2 != 0);
        }
        base += __popc(m1);
    }
    int m = base;
    int lead = any2;
    __syncwarp();
    if (lane == 0){
        pos[m] = Tt;
        if (lead) rowinfo[b*Tt] = (0<<16) | (m ? pos[0] : Tt);
        nvraw[b] = lead + m;
    }
    __syncwarp();
    for (int j = lane; j < m; j += 32){
        int s = pos[j], e = pos[j+1];
        rowinfo[b*Tt + lead + j] = (s<<16) | e;
    }
}

// ---------------- global compaction bookkeeping ---------------------------------
__global__ void combine2_kernel(const int* __restrict__ nvraw0, const int* __restrict__ nvraw1,
                                int* __restrict__ base0, int* __restrict__ base1,
                                int* __restrict__ lsm_nv, int* __restrict__ lsm_base,
                                int* __restrict__ rtot)
{
    if (threadIdx.x || blockIdx.x) return;
    int off = 0;
    int cnt = 0;
    for (int b=0;b<Bb;b++){
        int nv = nvraw0[b];
        if (nv > 0){ base0[b] = off; lsm_base[cnt] = off; lsm_nv[cnt] = nv; cnt++; off += nv; }
        else base0[b] = -1;
    }
    for (int k=cnt;k<Bb;k++) lsm_nv[k] = 0;
    cnt = 0;
    for (int b=0;b<Bb;b++){
        int nv = nvraw1[b];
        if (nv > 0){ base1[b] = off; lsm_base[Bb+cnt] = off; lsm_nv[Bb+cnt] = nv; cnt++; off += nv; }
        else base1[b] = -1;
    }
    for (int k=cnt;k<Bb;k++) lsm_nv[Bb+k] = 0;
    rtot[1] = off;
    rtot[0] = (off + 127) & ~127;   // Rpad (128-row tiles)
}

// ---------------- zero pooled pad rows [R, Rpad) (hi plane only) -----------------
__global__ void __launch_bounds__(256) padzero_kernel(
    const int* __restrict__ rtot, __half* __restrict__ ph)
{
    int row = rtot[1] + blockIdx.x;
    if (row >= rtot[0]) return;
    size_t off = (size_t)row*Hh;
    __half z = __float2half(0.f);
    for (int i = threadIdx.x; i < Hh; i += 256) ph[off+i] = z;
}

// ---------------- segment means -> globally compacted pooled rows (hi only) -----
// grid (Bb, 16, 2); z selects pass (labels vs pred)
__global__ void __launch_bounds__(256) pool2_kernel(
    const int* __restrict__ labels, const int* __restrict__ pred,
    const float* __restrict__ hidden,
    const int* __restrict__ ri0, const int* __restrict__ nv0arr, const int* __restrict__ b0arr,
    const int* __restrict__ ri1, const int* __restrict__ nv1arr, const int* __restrict__ b1arr,
    __half* __restrict__ ph)
{
    int b = blockIdx.x;
    int z = blockIdx.z;
    const int* lsrc   = (z ? pred : labels);
    const int* rowinfo = z ? ri1 : ri0;
    int d  = (z ? b1arr : b0arr)[b];
    if (d < 0) return;
    int nv = (z ? nv1arr : nv0arr)[b];
    __shared__ int labs[Tt];
    int tid = threadIdx.x;
    for (int i=tid;i<Tt;i+=256) labs[i] = lsrc[b*Tt+i];
    __syncthreads();
    int r0 = blockIdx.y * 32;
    int r1 = min(r0+32, nv);
    for (int r=r0; r<r1; r++){
        int info = rowinfo[b*Tt + r];
        int s = info >> 16, e = info & 0xffff;
        float a0=0.f,a1=0.f,a2=0.f;
        int cnt = 0;
        for (int t=s;t<e;t++){
            if (labs[t] != 0){
                cnt++;
                const float* hp = hidden + ((size_t)(b*Tt)+t)*Hh;
                a0 += hp[tid]; a1 += hp[tid+256]; a2 += hp[tid+512];
            }
        }
        float inv = 1.0f / (float)cnt;
        size_t off = ((size_t)(d + r))*Hh;
        ph[off+tid]     = __float2half_rn(a0*inv);
        ph[off+tid+256] = __float2half_rn(a1*inv);
        ph[off+tid+512] = __float2half_rn(a2*inv);
    }
}

// ---------------- row log-softmax over compacted sc ------------------------------
__global__ void __launch_bounds__(256) lsm_kernel(
    const float* __restrict__ sc, const int* __restrict__ lsm_nv,
    const int* __restrict__ lsm_base, float* __restrict__ out1, float* __restrict__ out2)
{
    int row = blockIdx.x*8 + (threadIdx.x >> 5);
    int p   = blockIdx.y;
    int lane = threadIdx.x & 31;
    int bb = row >> 9, t = row & 511;
    int nv = lsm_nv[p*Bb + bb];
    float* op = (p ? out2 : out1) + (size_t)row*Nn;
    if (t >= nv){
        const float CNEG = -7.6246189861593985f;   // -log(2048)
        float4 c4 = make_float4(CNEG,CNEG,CNEG,CNEG);
        for (int i=lane;i<Nn/4;i+=32) ((float4*)op)[i] = c4;
        return;
    }
    int srow = lsm_base[p*Bb + bb] + t;
    const float4* ip = (const float4*)(sc + (size_t)srow*Nn);
    float4 v[16];
    float m = -3.4e38f;
    #pragma unroll
    for (int i=0;i<16;i++){
        v[i] = ip[lane + i*32];
        m = fmaxf(m, fmaxf(fmaxf(v[i].x,v[i].y), fmaxf(v[i].z,v[i].w)));
    }
    #pragma unroll
    for (int off=16;off;off>>=1) m = fmaxf(m, __shfl_xor_sync(0xffffffffu, m, off));
    float s = 0.f;
    #pragma unroll
    for (int i=0;i<16;i++)
        s += expf(v[i].x-m)+expf(v[i].y-m)+expf(v[i].z-m)+expf(v[i].w-m);
    #pragma unroll
    for (int off=16;off;off>>=1) s += __shfl_xor_sync(0xffffffffu, s, off);
    float corr = m + logf(s);
    #pragma unroll
    for (int i=0;i<16;i++){
        float4 o = v[i];
        o.x-=corr; o.y-=corr; o.z-=corr; o.w-=corr;
        ((float4*)op)[lane + i*32] = o;
    }
}

// ---------------- host -------------------------------------------------------------
extern "C" void kernel_launch(void* const* d_in, const int* in_sizes, int n_in,
                              void* d_out, int out_size)
{
    (void)in_sizes; (void)n_in; (void)out_size;
    const int*   labels = (const int*)  d_in[0];
    const float* hidden = (const float*)d_in[1];
    const float* ent    = (const float*)d_in[2];
    const float* W1     = (const float*)d_in[3];
    const float* b1     = (const float*)d_in[4];
    const float* W2     = (const float*)d_in[5];
    const float* b2     = (const float*)d_in[6];
    const float* Wm     = (const float*)d_in[7];
    const float* Wd     = (const float*)d_in[8];

    float* out0 = (float*)d_out;
    float* s1o  = out0 + (size_t)BT*3;
    float* s2o  = s1o  + (size_t)BT*Nn;

    __half *enth,*entl,*w1h,*w1l,*wmh,*wml,*wdh,*wdl;
    __half *poolh,*pmh,*pdh,*pdl;
    float *gpart, *sc;
    int *pred, *ri0, *ri1, *nv0, *nv1, *b0, *b1a, *lnv, *lbs, *rtot;
    cudaGetSymbolAddress((void**)&enth, g_ent_h);  cudaGetSymbolAddress((void**)&entl, g_ent_l);
    cudaGetSymbolAddress((void**)&w1h,  g_W1_h);   cudaGetSymbolAddress((void**)&w1l,  g_W1_l);
    cudaGetSymbolAddress((void**)&wmh,  g_Wm_h);   cudaGetSymbolAddress((void**)&wml,  g_Wm_l);
    cudaGetSymbolAddress((void**)&wdh,  g_Wd_h);   cudaGetSymbolAddress((void**)&wdl,  g_Wd_l);
    cudaGetSymbolAddress((void**)&poolh,g_pool_h);
    cudaGetSymbolAddress((void**)&pmh,  g_pm_h);
    cudaGetSymbolAddress((void**)&pdh,  g_pd_h);   cudaGetSymbolAddress((void**)&pdl,  g_pd_l);
    cudaGetSymbolAddress((void**)&gpart,g_part);
    cudaGetSymbolAddress((void**)&sc,   g_sc);
    cudaGetSymbolAddress((void**)&pred, g_pred);
    cudaGetSymbolAddress((void**)&ri0,  g_rowinfo0);
    cudaGetSymbolAddress((void**)&ri1,  g_rowinfo1);
    cudaGetSymbolAddress((void**)&nv0,  g_nvraw0);
    cudaGetSymbolAddress((void**)&nv1,  g_nvraw1);
    cudaGetSymbolAddress((void**)&b0,   g_base0);
    cudaGetSymbolAddress((void**)&b1a,  g_base1);
    cudaGetSymbolAddress((void**)&lnv,  g_lsm_nv);
    cudaGetSymbolAddress((void**)&lbs,  g_lsm_base);
    cudaGetSymbolAddress((void**)&rtot, g_Rtot);

    cudaFuncSetAttribute((const void*)mma_gemm<EP_LOGITS,false,3,true>, cudaFuncAttributeMaxDynamicSharedMemorySize, SMEM_LOG);
    cudaFuncSetAttribute((const void*)mma_gemm<EP_PAD,false,2,false>,   cudaFuncAttributeMaxDynamicSharedMemorySize, SMEM_GEMM);
    cudaFuncSetAttribute((const void*)mma_gemm<EP_PAD,true,2,false>,    cudaFuncAttributeMaxDynamicSharedMemorySize, SMEM_GEMM);
    cudaFuncSetAttribute((const void*)mma_gemm<EP_PLAIN,true,2,false>,  cudaFuncAttributeMaxDynamicSharedMemorySize, SMEM_GEMM);

    const int NSPLIT = Hh*Hh + Nn*Hh + 2*Pp*Hh;

    // 1) fused weight splits (one launch)
    fsplit_kernel<<<(NSPLIT+255)/256, 256>>>(W1, ent, Wm, Wd,
        w1h, w1l, enth, entl, wmh, wml, wdh, wdl);

    // 2) fused gemm1: h = relu(x@W1^T+b1) in-flight (fp32 A converted in-stage);
    //    gpart[cb] = h_block @ W2^T  (h never materialized)
    mma_gemm<EP_LOGITS,false,3,true><<<dim3(Hh/128, BT/128), NTHR, SMEM_LOG>>>(
        nullptr, nullptr, hidden, w1h, w1l, gpart, nullptr, nullptr,
        Hh, Hh, 3, Hh, Hh, Hh, b1, nullptr, W2);

    // 3) bio logits -> out0 + predicted labels
    logits2_kernel<<<BT/256, 256>>>(gpart, b2, out0, pred);

    // 4) pd = ent @ Wd^T -> half hi/lo planes, K-padded to KP (2-term)
    mma_gemm<EP_PAD,false,2,false><<<dim3(3, Nn/128), NTHR, SMEM_GEMM>>>(
        enth, entl, nullptr, wdh, wdl, nullptr, pdh, pdl,
        Hh, Hh, KP, Hh, Pp, Pp, nullptr, nullptr, nullptr);

    // 5) both scans (one launch), compaction, both pools (one launch), pad-zero
    scan2_kernel<<<dim3(Bb, 2), 32>>>(labels, pred, ri0, nv0, ri1, nv1);
    combine2_kernel<<<1, 1>>>(nv0, nv1, b0, b1a, lnv, lbs, rtot);
    pool2_kernel<<<dim3(Bb, 16, 2), 256>>>(labels, pred, hidden,
        ri0, nv0, b0, ri1, nv1, b1a, poolh);
    padzero_kernel<<<128, 256>>>(rtot, poolh);

    // 6) pm = pooled @ Wm^T over compacted rows — 2-term, hi-plane output only
    mma_gemm<EP_PAD,true,2,false><<<dim3(3, BT2/128), NTHR, SMEM_GEMM>>>(
        poolh, nullptr, nullptr, wmh, wml, nullptr, pmh, nullptr,
        Hh, Hh, KP, Hh, Pp, Pp, nullptr, rtot, nullptr);

    // 7) sc = pm @ pd^T over compacted rows — 2-term
    mma_gemm<EP_PLAIN,true,2,false><<<dim3(Nn/128, BT2/128), NTHR, SMEM_GEMM>>>(
        pmh, nullptr, nullptr, pdh, pdl, sc, nullptr, nullptr,
        KP, KP, Nn, KP, Nn, Nn, nullptr, rtot, nullptr);

    // 8) log-softmax scatter to both outputs
    lsm_kernel<<<dim3(BT/8, 2), 256>>>(sc, lnv, lbs, s1o, s2o);
}

// round 16
// speedup vs baseline: 1.0795x; 1.0205x over previous
#include <cuda_runtime.h>
#include <cuda_fp16.h>
#include <math.h>
#include <stdint.h>

#define Bb 64
#define Tt 512
#define Hh 768
#define Nn 2048
#define Pp 300
#define KP 320
#define BT (Bb*Tt)
#define BT2 (2*BT)

// ---------------- scratch (device globals; no allocation allowed) ----------
__device__ __half g_W1_h[Hh*Hh],            g_W1_l[Hh*Hh];
__device__ __half g_Wm_h[Pp*Hh],            g_Wm_l[Pp*Hh];
__device__ __half g_Wd_h[Pp*Hh],            g_Wd_l[Pp*Hh];
__device__ __half g_pool_h[(size_t)BT2*Hh];
__device__ __half g_pm_h[(size_t)BT2*KP];
__device__ __half g_pd_h[(size_t)Nn*KP],    g_pd_l[(size_t)Nn*KP];
__device__ float  g_part[(size_t)6*BT*3];   // logits partials per col-tile
__device__ __half g_sc[(size_t)BT2*Nn];     // scores, fp16 (lsm-consistent quantization)
__device__ int    g_pred[BT];
__device__ int    g_rowinfo0[BT], g_rowinfo1[BT];
__device__ int    g_nvraw0[Bb],  g_nvraw1[Bb];
__device__ int    g_base0[Bb],   g_base1[Bb];
__device__ int    g_lsm_nv[2*Bb], g_lsm_base[2*Bb];
__device__ int    g_Rtot[4];                     // [0]=Rpad  [1]=R

// ---------------- helpers ----------------------------------------------------
__device__ __forceinline__ uint32_t smem_u32(const void* p){
    uint32_t a;
    asm("{ .reg .u64 t; cvta.to.shared.u64 t, %1; cvt.u32.u64 %0, t; }" : "=r"(a) : "l"(p));
    return a;
}
__device__ __forceinline__ void cp_async16(uint32_t dst, const void* src, bool ok){
    int sz = ok ? 16 : 0;   // src-size 0 -> zero-fill 16B
    asm volatile("cp.async.cg.shared.global [%0], [%1], 16, %2;" :: "r"(dst), "l"(src), "r"(sz));
}
__device__ __forceinline__ void cp_commit(){ asm volatile("cp.async.commit_group;" ::: "memory"); }
template<int N> __device__ __forceinline__ void cp_wait(){ asm volatile("cp.async.wait_group %0;" :: "n"(N) : "memory"); }

__device__ __forceinline__ void ldsm4(uint32_t* r, uint32_t addr){
    asm volatile("ldmatrix.sync.aligned.m8n8.x4.shared.b16 {%0,%1,%2,%3}, [%4];"
        : "=r"(r[0]), "=r"(r[1]), "=r"(r[2]), "=r"(r[3]) : "r"(addr));
}
__device__ __forceinline__ void mma16(float* d, const uint32_t* a, uint32_t b0, uint32_t b1){
    asm volatile(
        "mma.sync.aligned.m16n8k16.row.col.f32.f16.f16.f32 "
        "{%0,%1,%2,%3}, {%4,%5,%6,%7}, {%8,%9}, {%0,%1,%2,%3};"
        : "+f"(d[0]), "+f"(d[1]), "+f"(d[2]), "+f"(d[3])
        : "r"(a[0]), "r"(a[1]), "r"(a[2]), "r"(a[3]), "r"(b0), "r"(b1));
}
__device__ __forceinline__ void split16(float v, __half& h, __half& l){
    h = __float2half_rn(v);
    l = __float2half_rn(v - __half2float(h));
}

// ---------------- fp16 GEMM: C[M,N] = A[M,K] @ B[N,K]^T ----------------------
// CTA tile 128x128, BK=32, 8 warps (2m x 4n), warp tile 64x32, 3-stage cp.async,
// __launch_bounds__(256,2) -> <=128 regs -> 2 CTAs/SM.
// EP_LOGITS: fused relu(h)+W2 projection -> per-col-tile partials.
// EP_PAD: half hi (+lo if Cl) output with Nreal column zeroing.
// CVT: A arrives as raw fp32; 2-round in-stage conversion to interleaved h/l
//      planes (per-64-row groups: h at group*8192, l at +4096).
enum { EP_LOGITS = 0, EP_PAD = 1 };
#define ST_ALO 8192
#define ST_B   16384
#define ST_BLO 8192      // relative to ST_B
#define STAGE  32768
#define SMEM_GEMM (3*STAGE)              // 98304
#define SMEM_LOG  (3*STAGE + 6144 + 1536) // + psum[4][128][3] + w2s[3][128]
#define NTHR 256

template<int EPI, bool ROWMASK, int TERMS, bool CVT>
__global__ void __launch_bounds__(NTHR, 2) mma_gemm(
    const __half* __restrict__ Ah, const __half* __restrict__ Al,
    const float* __restrict__ Afp,
    const __half* __restrict__ Bh, const __half* __restrict__ Bl,
    float* __restrict__ C, __half* __restrict__ Ch, __half* __restrict__ Cl,
    int lda, int ldb, int ldc, int K, int Nreal, int NBreal,
    const float* __restrict__ bias, const int* __restrict__ rtot,
    const float* __restrict__ w2)
{
    extern __shared__ char smem[];
    const int m0 = blockIdx.y * 128, n0 = blockIdx.x * 128;
    const int tid = threadIdx.x;
    if (ROWMASK){
        if (m0 >= rtot[0]) return;     // beyond compacted rows
    }
    const uint32_t sb0 = smem_u32(smem);
    const int warp = tid >> 5, lane = tid & 31;
    const int wm = warp >> 2, wn = warp & 3;     // 2 x 4 warp grid, warp tile 64x32
    const int lr = lane >> 2, lc = lane & 3;

    float* psum = (float*)(smem + 3*STAGE);          // [4][128][3]
    float* w2s  = (float*)(smem + 3*STAGE + 6144);   // [3][128]
    if (EPI == EP_LOGITS && tid < 128){
        #pragma unroll
        for (int c = 0; c < 3; c++) w2s[c*128 + tid] = w2[c*Hh + n0 + tid];
    }

    float acc[4][4][4];
    #pragma unroll
    for (int i=0;i<4;i++)
        #pragma unroll
        for (int j=0;j<4;j++)
            #pragma unroll
            for (int q=0;q<4;q++) acc[i][j][q] = 0.f;

    const int arl = (lane & 7) + ((lane >> 3) & 1) * 8;
    const int acs = lane >> 4;
    const int nrl = (lane & 7) + (lane >> 4) * 8;
    const int bcs = (lane >> 3) & 1;
    uint32_t aoff[4], boff[2];
    #pragma unroll
    for (int mt = 0; mt < 4; mt++){
        int r = wm*64 + mt*16 + arl;
        int swz = acs ^ (r & 3) ^ ((r >> 2) & 1);
        if (CVT) aoff[mt] = (uint32_t)(((r >> 6) << 13) + ((r & 63) << 6) + (swz << 4));
        else     aoff[mt] = (uint32_t)((r << 6) + (swz << 4));
    }
    #pragma unroll
    for (int nb = 0; nb < 2; nb++){
        int r = wn*32 + nb*16 + nrl;
        boff[nb] = (uint32_t)ST_B + (uint32_t)((r << 6) + ((bcs ^ (r & 3) ^ ((r >> 2) & 1)) << 4));
    }
    const uint32_t ALO = CVT ? 4096u : (uint32_t)ST_ALO;

    auto load_tile = [&](int kt, int s){
        const int k0 = kt * 32;
        const uint32_t sbs = sb0 + (uint32_t)s * STAGE;
        if (CVT){
            #pragma unroll
            for (int j = 0; j < 8; j++){
                int idx = tid + j*NTHR;                 // 0..2047
                if (idx < 1024){                        // raw fp32 A: 128 rows x 8 float4
                    int row = idx >> 3, q = idx & 7;
                    uint32_t so = sbs + (uint32_t)(row*128 + q*16);
                    cp_async16(so, Afp + (size_t)(m0 + row)*lda + k0 + q*4, true);
                } else {                                // B planes: Bh, Bl
                    int b   = idx - 1024;
                    int pl  = b >> 9;
                    int rem = b & 511;
                    int row = rem >> 2, c = rem & 3;
                    int c2  = c ^ (row & 3) ^ ((row >> 2) & 1);
                    uint32_t so = sbs + (uint32_t)(ST_B + pl*ST_BLO + row*64 + c2*16);
                    bool ok = (n0 + row) < NBreal;
                    const __half* base = pl ? Bl : Bh;
                    const __half* src = ok ? (base + (size_t)(n0 + row)*ldb + k0 + c*8) : base;
                    cp_async16(so, src, ok);
                }
            }
        } else if (TERMS == 3){
            #pragma unroll
            for (int j = 0; j < 8; j++){
                int idx = tid + j*NTHR;
                if (idx < 1024){                        // A planes: Ah, Al
                    int pl  = idx >> 9;
                    int rem = idx & 511;
                    int row = rem >> 2, c = rem & 3;
                    int c2  = c ^ (row & 3) ^ ((row >> 2) & 1);
                    uint32_t so = sbs + (uint32_t)(pl*ST_ALO + row*64 + c2*16);
                    const __half* src = (pl ? Al : Ah) + (size_t)(m0 + row)*lda + k0 + c*8;
                    cp_async16(so, src, true);
                } else {
                    int b   = idx - 1024;
                    int pl  = b >> 9;
                    int rem = b & 511;
                    int row = rem >> 2, c = rem & 3;
                    int c2  = c ^ (row & 3) ^ ((row >> 2) & 1);
                    uint32_t so = sbs + (uint32_t)(ST_B + pl*ST_BLO + row*64 + c2*16);
                    bool ok = (n0 + row) < NBreal;
                    const __half* base = pl ? Bl : Bh;
                    const __half* src = ok ? (base + (size_t)(n0 + row)*ldb + k0 + c*8) : base;
                    cp_async16(so, src, ok);
                }
            }
        } else {   // TERMS == 2: planes Ah, Bh, Bl only
            #pragma unroll
            for (int j = 0; j < 6; j++){
                int idx = tid + j*NTHR;
                if (idx < 512){                          // Ah
                    int row = idx >> 2, c = idx & 3;
                    int c2  = c ^ (row & 3) ^ ((row >> 2) & 1);
                    uint32_t so = sbs + (uint32_t)(row*64 + c2*16);
                    cp_async16(so, Ah + (size_t)(m0 + row)*lda + k0 + c*8, true);
                } else {
                    int b   = idx - 512;
                    int pl  = b >> 9;
                    int rem = b & 511;
                    int row = rem >> 2, c = rem & 3;
                    int c2  = c ^ (row & 3) ^ ((row >> 2) & 1);
                    uint32_t so = sbs + (uint32_t)(ST_B + pl*ST_BLO + row*64 + c2*16);
                    bool ok = (n0 + row) < NBreal;
                    const __half* base = pl ? Bl : Bh;
                    const __half* src = ok ? (base + (size_t)(n0 + row)*ldb + k0 + c*8) : base;
                    cp_async16(so, src, ok);
                }
            }
        }
        cp_commit();
    };

    const int nkt = K >> 5;
    load_tile(0, 0);
    if (nkt > 1) load_tile(1, 1);
    for (int kt = 0; kt < nkt; kt++){
        const int s = kt % 3;
        if (kt + 1 < nkt) cp_wait<1>(); else cp_wait<0>();
        __syncthreads();

        if (CVT){
            // in-stage fp32 -> interleaved h/l conversion, 2 row-group rounds
            char* sp = smem + s*STAGE;
            #pragma unroll
            for (int rnd = 0; rnd < 2; rnd++){
                int r   = rnd*64 + (tid >> 2);
                int seg = tid & 3;
                const float4* fp = (const float4*)(sp + (r & 63)*128 + (r >> 6)*8192 + seg*32);
                float4 f0 = fp[0], f1 = fp[1];
                __syncthreads();
                float f[8] = {f0.x,f0.y,f0.z,f0.w,f1.x,f1.y,f1.z,f1.w};
                __half hv[8], lv[8];
                #pragma unroll
                for (int j = 0; j < 8; j++) split16(f[j], hv[j], lv[j]);
                int c2 = seg ^ (r & 3) ^ ((r >> 2) & 1);
                char* hp = sp + ((r >> 6) << 13) + ((r & 63) << 6) + (c2 << 4);
                *(uint4*)hp          = *(uint4*)hv;
                *(uint4*)(hp + 4096) = *(uint4*)lv;
                __syncthreads();
            }
        }

        if (kt + 2 < nkt) load_tile(kt + 2, (kt + 2) % 3);
        const uint32_t sbs = sb0 + (uint32_t)s * STAGE;

        #pragma unroll
        for (int ks = 0; ks < 2; ks++){
            const uint32_t kx = (uint32_t)(ks << 5);
            uint32_t bhf[2][4], blf[2][4];
            #pragma unroll
            for (int nb = 0; nb < 2; nb++){
                uint32_t t = (sbs + boff[nb]) ^ kx;
                ldsm4(bhf[nb], t);
                ldsm4(blf[nb], t + ST_BLO);
            }
            #pragma unroll
            for (int mt = 0; mt < 4; mt++){
                uint32_t ahf[4], alf[4];
                uint32_t t = (sbs + aoff[mt]) ^ kx;
                ldsm4(ahf, t);
                if (TERMS == 3) ldsm4(alf, t + ALO);
                #pragma unroll
                for (int nt = 0; nt < 4; nt++){
                    const int nb = nt >> 1, p = (nt & 1) * 2;
                    float* d = acc[mt][nt];
                    mma16(d, ahf, bhf[nb][p], bhf[nb][p+1]);       // hi*hi
                    mma16(d, ahf, blf[nb][p], blf[nb][p+1]);       // hi*lo
                    if (TERMS == 3)
                        mma16(d, alf, bhf[nb][p], bhf[nb][p+1]);   // lo*hi
                }
            }
        }
        if (CVT) __syncthreads();   // stage s fully consumed before reuse as fp32 target
    }

    if (EPI == EP_LOGITS){
        // fused: v = relu(acc + b1); partial[c] = sum_col v * W2[c][col]
        float w2v[4][2][3];
        float bv[4][2];
        #pragma unroll
        for (int nt = 0; nt < 4; nt++){
            int colL = wn*32 + nt*8 + lc*2;
            #pragma unroll
            for (int j = 0; j < 2; j++){
                bv[nt][j] = bias[n0 + colL + j];
                #pragma unroll
                for (int c = 0; c < 3; c++) w2v[nt][j][c] = w2s[c*128 + colL + j];
            }
        }
        #pragma unroll
        for (int mt = 0; mt < 4; mt++){
            float pA[3] = {0.f,0.f,0.f}, pB[3] = {0.f,0.f,0.f};
            #pragma unroll
            for (int nt = 0; nt < 4; nt++){
                float* a = acc[mt][nt];
                float v0 = a[0] + bv[nt][0]; v0 = v0 > 0.f ? v0 : 0.f;
                float v1 = a[1] + bv[nt][1]; v1 = v1 > 0.f ? v1 : 0.f;
                float v2 = a[2] + bv[nt][0]; v2 = v2 > 0.f ? v2 : 0.f;
                float v3 = a[3] + bv[nt][1]; v3 = v3 > 0.f ? v3 : 0.f;
                #pragma unroll
                for (int c = 0; c < 3; c++){
                    pA[c] += v0*w2v[nt][0][c] + v1*w2v[nt][1][c];
                    pB[c] += v2*w2v[nt][0][c] + v3*w2v[nt][1][c];
                }
            }
            #pragma unroll
            for (int off = 1; off <= 2; off <<= 1){
                #pragma unroll
                for (int c = 0; c < 3; c++){
                    pA[c] += __shfl_xor_sync(0xffffffffu, pA[c], off);
                    pB[c] += __shfl_xor_sync(0xffffffffu, pB[c], off);
                }
            }
            if (lc == 0){
                int rA = wm*64 + mt*16 + lr;
                #pragma unroll
                for (int c = 0; c < 3; c++){
                    psum[(wn*128 + rA)*3 + c]     = pA[c];
                    psum[(wn*128 + rA + 8)*3 + c] = pB[c];
                }
            }
        }
        __syncthreads();
        for (int r = tid; r < 128; r += NTHR){
            #pragma unroll
            for (int c = 0; c < 3; c++){
                float g = psum[(0*128 + r)*3 + c];
                g += psum[(1*128 + r)*3 + c];
                g += psum[(2*128 + r)*3 + c];
                g += psum[(3*128 + r)*3 + c];
                C[((size_t)blockIdx.x*BT + (m0 + r))*3 + c] = g;
            }
        }
        return;
    }

    // EP_PAD epilogue: half hi (+lo if provided), zero pad columns
    #pragma unroll
    for (int mt = 0; mt < 4; mt++){
        #pragma unroll
        for (int nt = 0; nt < 4; nt++){
            int row = m0 + wm*64 + mt*16 + lr;
            int col = n0 + wn*32 + nt*8 + lc*2;
            float* a = acc[mt][nt];
            if (col + 2 <= ldc){
                float v0 = (col   < Nreal) ? a[0] : 0.f;
                float v1 = (col+1 < Nreal) ? a[1] : 0.f;
                float v2 = (col   < Nreal) ? a[2] : 0.f;
                float v3 = (col+1 < Nreal) ? a[3] : 0.f;
                __half h0,l0,h1,l1,h2,l2,h3,l3;
                split16(v0,h0,l0); split16(v1,h1,l1);
                split16(v2,h2,l2); split16(v3,h3,l3);
                *(__half2*)&Ch[(size_t)row*ldc + col]     = __halves2half2(h0, h1);
                *(__half2*)&Ch[(size_t)(row+8)*ldc + col] = __halves2half2(h2, h3);
                if (Cl){
                    *(__half2*)&Cl[(size_t)row*ldc + col]     = __halves2half2(l0, l1);
                    *(__half2*)&Cl[(size_t)(row+8)*ldc + col] = __halves2half2(l2, l3);
                }
            }
        }
    }
}

// ---------------- fused weight split: W1 | Wm | Wd ------------------------------
__global__ void __launch_bounds__(256) fsplit_kernel(
    const float* __restrict__ W1, const float* __restrict__ Wm, const float* __restrict__ Wd,
    __half* __restrict__ w1h, __half* __restrict__ w1l,
    __half* __restrict__ wmh, __half* __restrict__ wml,
    __half* __restrict__ wdh, __half* __restrict__ wdl)
{
    const int n1 = Hh*Hh, n2 = n1 + Pp*Hh, n3 = n2 + Pp*Hh;
    int i = blockIdx.x*256 + threadIdx.x;
    const float* src; __half *dh, *dl; int off;
    if (i < n1){ src = W1; dh = w1h; dl = w1l; off = i; }
    else if (i < n2){ src = Wm;  dh = wmh;  dl = wml;  off = i - n1; }
    else if (i < n3){ src = Wd;  dh = wdh;  dl = wdl;  off = i - n2; }
    else return;
    __half hv, lv; split16(src[off], hv, lv); dh[off] = hv; dl[off] = lv;
}

// ---------------- final 3-class head: sum partials + log_softmax + argmax -------
__global__ void __launch_bounds__(256) logits2_kernel(
    const float* __restrict__ gpart, const float* __restrict__ b2,
    float* __restrict__ out0, int* __restrict__ pred)
{
    int row = blockIdx.x*256 + threadIdx.x;
    float s[3];
    #pragma unroll
    for (int c = 0; c < 3; c++) s[c] = b2[c];
    #pragma unroll
    for (int k = 0; k < 6; k++)
        #pragma unroll
        for (int c = 0; c < 3; c++)
            s[c] += gpart[((size_t)k*BT + row)*3 + c];
    float m = fmaxf(s[0], fmaxf(s[1], s[2]));
    float lse = m + logf(expf(s[0]-m)+expf(s[1]-m)+expf(s[2]-m));
    size_t o = (size_t)row*3;
    out0[o+0] = s[0] - lse; out0[o+1] = s[1] - lse; out0[o+2] = s[2] - lse;
    int idx = 0; float best = s[0];
    if (s[1] > best){ best = s[1]; idx = 1; }
    if (s[2] > best){ idx = 2; }
    pred[row] = idx;
}

// ---------------- BIO segment scan, both passes (grid.y selects source) ---------
__global__ void scan2_kernel(const int* __restrict__ labels, const int* __restrict__ pred,
                             int* __restrict__ ri0, int* __restrict__ nv0,
                             int* __restrict__ ri1, int* __restrict__ nv1)
{
    __shared__ int pos[513];
    int b = blockIdx.x, lane = threadIdx.x;
    const int* lab = (blockIdx.y ? pred : labels) + b*Tt;
    int* rowinfo = blockIdx.y ? ri1 : ri0;
    int* nvraw   = blockIdx.y ? nv1 : nv0;
    int base = 0;
    int first1 = Tt;
    int any2 = 0;
    #pragma unroll 1
    for (int c = 0; c < Tt/32; c++){
        int l = lab[c*32 + lane];
        unsigned m1 = __ballot_sync(0xffffffffu, l == 1);
        unsigned m2 = __ballot_sync(0xffffffffu, l == 2);
        if (l == 1) pos[base + __popc(m1 & ((1u<<lane)-1))] = c*32 + lane;
        if (first1 == Tt){
            if (m1){
                int fl = __ffs(m1) - 1;
                first1 = c*32 + fl;
                any2 |= (m2 & ((1u<<fl)-1)) != 0;
            } else any2 |= (m2 != 0);
        }
        base += __popc(m1);
    }
    int m = base;
    int lead = any2;
    __syncwarp();
    if (lane == 0){
        pos[m] = Tt;
        if (lead) rowinfo[b*Tt] = (0<<16) | (m ? pos[0] : Tt);
        nvraw[b] = lead + m;
    }
    __syncwarp();
    for (int j = lane; j < m; j += 32){
        int s = pos[j], e = pos[j+1];
        rowinfo[b*Tt + lead + j] = (s<<16) | e;
    }
}

// ---------------- global compaction bookkeeping ---------------------------------
__global__ void combine2_kernel(const int* __restrict__ nvraw0, const int* __restrict__ nvraw1,
                                int* __restrict__ base0, int* __restrict__ base1,
                                int* __restrict__ lsm_nv, int* __restrict__ lsm_base,
                                int* __restrict__ rtot)
{
    if (threadIdx.x || blockIdx.x) return;
    int off = 0;
    int cnt = 0;
    for (int b=0;b<Bb;b++){
        int nv = nvraw0[b];
        if (nv > 0){ base0[b] = off; lsm_base[cnt] = off; lsm_nv[cnt] = nv; cnt++; off += nv; }
        else base0[b] = -1;
    }
    for (int k=cnt;k<Bb;k++) lsm_nv[k] = 0;
    cnt = 0;
    for (int b=0;b<Bb;b++){
        int nv = nvraw1[b];
        if (nv > 0){ base1[b] = off; lsm_base[Bb+cnt] = off; lsm_nv[Bb+cnt] = nv; cnt++; off += nv; }
        else base1[b] = -1;
    }
    for (int k=cnt;k<Bb;k++) lsm_nv[Bb+k] = 0;
    rtot[1] = off;
    rtot[0] = (off + 127) & ~127;   // Rpad (128-row tiles)
}

// ---------------- zero pooled pad rows [R, Rpad) (hi plane only) -----------------
__global__ void __launch_bounds__(256) padzero_kernel(
    const int* __restrict__ rtot, __half* __restrict__ ph)
{
    int row = rtot[1] + blockIdx.x;
    if (row >= rtot[0]) return;
    size_t off = (size_t)row*Hh;
    __half z = __float2half(0.f);
    for (int i = threadIdx.x; i < Hh; i += 256) ph[off+i] = z;
}

// ---------------- segment means -> globally compacted pooled rows (hi only) -----
// grid (Bb, 16, 2); z selects pass (labels vs pred)
__global__ void __launch_bounds__(256) pool2_kernel(
    const int* __restrict__ labels, const int* __restrict__ pred,
    const float* __restrict__ hidden,
    const int* __restrict__ ri0, const int* __restrict__ nv0arr, const int* __restrict__ b0arr,
    const int* __restrict__ ri1, const int* __restrict__ nv1arr, const int* __restrict__ b1arr,
    __half* __restrict__ ph)
{
    int b = blockIdx.x;
    int z = blockIdx.z;
    const int* lsrc   = (z ? pred : labels);
    const int* rowinfo = z ? ri1 : ri0;
    int d  = (z ? b1arr : b0arr)[b];
    if (d < 0) return;
    int nv = (z ? nv1arr : nv0arr)[b];
    __shared__ int labs[Tt];
    int tid = threadIdx.x;
    for (int i=tid;i<Tt;i+=256) labs[i] = lsrc[b*Tt+i];
    __syncthreads();
    int r0 = blockIdx.y * 32;
    int r1 = min(r0+32, nv);
    for (int r=r0; r<r1; r++){
        int info = rowinfo[b*Tt + r];
        int s = info >> 16, e = info & 0xffff;
        float a0=0.f,a1=0.f,a2=0.f;
        int cnt = 0;
        for (int t=s;t<e;t++){
            if (labs[t] != 0){
                cnt++;
                const float* hp = hidden + ((size_t)(b*Tt)+t)*Hh;
                a0 += hp[tid]; a1 += hp[tid+256]; a2 += hp[tid+512];
            }
        }
        float inv = 1.0f / (float)cnt;
        size_t off = ((size_t)(d + r))*Hh;
        ph[off+tid]     = __float2half_rn(a0*inv);
        ph[off+tid+256] = __float2half_rn(a1*inv);
        ph[off+tid+512] = __float2half_rn(a2*inv);
    }
}

// ---------------- row log-softmax over compacted fp16 sc -------------------------
__global__ void __launch_bounds__(256) lsm_kernel(
    const __half* __restrict__ sc, const int* __restrict__ lsm_nv,
    const int* __restrict__ lsm_base, float* __restrict__ out1, float* __restrict__ out2)
{
    int row = blockIdx.x*8 + (threadIdx.x >> 5);
    int p   = blockIdx.y;
    int lane = threadIdx.x & 31;
    int bb = row >> 9, t = row & 511;
    int nv = lsm_nv[p*Bb + bb];
    float* op = (p ? out2 : out1) + (size_t)row*Nn;
    if (t >= nv){
        const float CNEG = -7.6246189861593985f;   // -log(2048)
        float4 c4 = make_float4(CNEG,CNEG,CNEG,CNEG);
        for (int i=lane;i<Nn/4;i+=32) ((float4*)op)[i] = c4;
        return;
    }
    int srow = lsm_base[p*Bb + bb] + t;
    const uint2* ip = (const uint2*)(sc + (size_t)srow*Nn);  // 4 halves per uint2
    float v[64];
    float m = -3.4e38f;
    #pragma unroll
    for (int i=0;i<16;i++){
        uint2 r = ip[lane + i*32];
        float2 f0 = __half22float2(*(__half2*)&r.x);
        float2 f1 = __half22float2(*(__half2*)&r.y);
        v[i*4+0]=f0.x; v[i*4+1]=f0.y; v[i*4+2]=f1.x; v[i*4+3]=f1.y;
        m = fmaxf(m, fmaxf(fmaxf(f0.x,f0.y), fmaxf(f1.x,f1.y)));
    }
    #pragma unroll
    for (int off=16;off;off>>=1) m = fmaxf(m, __shfl_xor_sync(0xffffffffu, m, off));
    float s = 0.f;
    #pragma unroll
    for (int i=0;i<64;i++) s += expf(v[i]-m);
    #pragma unroll
    for (int off=16;off;off>>=1) s += __shfl_xor_sync(0xffffffffu, s, off);
    float corr = m + logf(s);
    #pragma unroll
    for (int i=0;i<16;i++){
        float4 o = make_float4(v[i*4]-corr, v[i*4+1]-corr, v[i*4+2]-corr, v[i*4+3]-corr);
        ((float4*)op)[lane + i*32] = o;
    }
}

// ---------------- host -------------------------------------------------------------
extern "C" void kernel_launch(void* const* d_in, const int* in_sizes, int n_in,
                              void* d_out, int out_size)
{
    (void)in_sizes; (void)n_in; (void)out_size;
    const int*   labels = (const int*)  d_in[0];
    const float* hidden = (const float*)d_in[1];
    const float* ent    = (const float*)d_in[2];
    const float* W1     = (const float*)d_in[3];
    const float* b1     = (const float*)d_in[4];
    const float* W2     = (const float*)d_in[5];
    const float* b2     = (const float*)d_in[6];
    const float* Wm     = (const float*)d_in[7];
    const float* Wd     = (const float*)d_in[8];

    float* out0 = (float*)d_out;
    float* s1o  = out0 + (size_t)BT*3;
    float* s2o  = s1o  + (size_t)BT*Nn;

    __half *w1h,*w1l,*wmh,*wml,*wdh,*wdl;
    __half *poolh,*pmh,*pdh,*pdl,*sc;
    float *gpart;
    int *pred, *ri0, *ri1, *nv0, *nv1, *b0, *b1a, *lnv, *lbs, *rtot;
    cudaGetSymbolAddress((void**)&w1h,  g_W1_h);   cudaGetSymbolAddress((void**)&w1l,  g_W1_l);
    cudaGetSymbolAddress((void**)&wmh,  g_Wm_h);   cudaGetSymbolAddress((void**)&wml,  g_Wm_l);
    cudaGetSymbolAddress((void**)&wdh,  g_Wd_h);   cudaGetSymbolAddress((void**)&wdl,  g_Wd_l);
    cudaGetSymbolAddress((void**)&poolh,g_pool_h);
    cudaGetSymbolAddress((void**)&pmh,  g_pm_h);
    cudaGetSymbolAddress((void**)&pdh,  g_pd_h);   cudaGetSymbolAddress((void**)&pdl,  g_pd_l);
    cudaGetSymbolAddress((void**)&gpart,g_part);
    cudaGetSymbolAddress((void**)&sc,   g_sc);
    cudaGetSymbolAddress((void**)&pred, g_pred);
    cudaGetSymbolAddress((void**)&ri0,  g_rowinfo0);
    cudaGetSymbolAddress((void**)&ri1,  g_rowinfo1);
    cudaGetSymbolAddress((void**)&nv0,  g_nvraw0);
    cudaGetSymbolAddress((void**)&nv1,  g_nvraw1);
    cudaGetSymbolAddress((void**)&b0,   g_base0);
    cudaGetSymbolAddress((void**)&b1a,  g_base1);
    cudaGetSymbolAddress((void**)&lnv,  g_lsm_nv);
    cudaGetSymbolAddress((void**)&lbs,  g_lsm_base);
    cudaGetSymbolAddress((void**)&rtot, g_Rtot);

    cudaFuncSetAttribute((const void*)mma_gemm<EP_LOGITS,false,3,true>, cudaFuncAttributeMaxDynamicSharedMemorySize, SMEM_LOG);
    cudaFuncSetAttribute((const void*)mma_gemm<EP_PAD,false,2,true>,    cudaFuncAttributeMaxDynamicSharedMemorySize, SMEM_GEMM);
    cudaFuncSetAttribute((const void*)mma_gemm<EP_PAD,true,2,false>,    cudaFuncAttributeMaxDynamicSharedMemorySize, SMEM_GEMM);

    const int NSPLIT = Hh*Hh + 2*Pp*Hh;

    // 1) fused weight splits (W1, Wm, Wd)
    fsplit_kernel<<<(NSPLIT+255)/256, 256>>>(W1, Wm, Wd, w1h, w1l, wmh, wml, wdh, wdl);

    // 2) fused gemm1: h = relu(x@W1^T+b1) in-flight (fp32 A converted in-stage);
    //    gpart[cb] = h_block @ W2^T  (h never materialized)
    mma_gemm<EP_LOGITS,false,3,true><<<dim3(Hh/128, BT/128), NTHR, SMEM_LOG>>>(
        nullptr, nullptr, hidden, w1h, w1l, gpart, nullptr, nullptr,
        Hh, Hh, 3, Hh, Hh, Hh, b1, nullptr, W2);

    // 3) bio logits -> out0 + predicted labels
    logits2_kernel<<<BT/256, 256>>>(gpart, b2, out0, pred);

    // 4) pd = ent @ Wd^T -> half hi/lo planes, K-padded to KP (2-term, ent CVT'd in-kernel)
    mma_gemm<EP_PAD,false,2,true><<<dim3(3, Nn/128), NTHR, SMEM_GEMM>>>(
        nullptr, nullptr, ent, wdh, wdl, nullptr, pdh, pdl,
        Hh, Hh, KP, Hh, Pp, Pp, nullptr, nullptr, nullptr);

    // 5) both scans (one launch), compaction, both pools (one launch), pad-zero
    scan2_kernel<<<dim3(Bb, 2), 32>>>(labels, pred, ri0, nv0, ri1, nv1);
    combine2_kernel<<<1, 1>>>(nv0, nv1, b0, b1a, lnv, lbs, rtot);
    pool2_kernel<<<dim3(Bb, 16, 2), 256>>>(labels, pred, hidden,
        ri0, nv0, b0, ri1, nv1, b1a, poolh);
    padzero_kernel<<<128, 256>>>(rtot, poolh);

    // 6) pm = pooled @ Wm^T over compacted rows — 2-term, hi-plane output only
    mma_gemm<EP_PAD,true,2,false><<<dim3(3, BT2/128), NTHR, SMEM_GEMM>>>(
        poolh, nullptr, nullptr, wmh, wml, nullptr, pmh, nullptr,
        Hh, Hh, KP, Hh, Pp, Pp, nullptr, rtot, nullptr);

    // 7) sc = pm @ pd^T over compacted rows — 2-term, fp16 output
    mma_gemm<EP_PAD,true,2,false><<<dim3(Nn/128, BT2/128), NTHR, SMEM_GEMM>>>(
        pmh, nullptr, nullptr, pdh, pdl, nullptr, sc, nullptr,
        KP, KP, Nn, KP, Nn, Nn, nullptr, rtot, nullptr);

    // 8) log-softmax scatter to both outputs
    lsm_kernel<<<dim3(BT/8, 2), 256>>>(sc, lnv, lbs, s1o, s2o);
}

// round 17
// speedup vs baseline: 1.1348x; 1.0513x over previous
#include <cuda_runtime.h>
#include <cuda_fp16.h>
#include <math.h>
#include <stdint.h>

#define Bb 64
#define Tt 512
#define Hh 768
#define Nn 2048
#define Pp 300
#define KP 320
#define BT (Bb*Tt)
#define BT2 (2*BT)

// ---------------- scratch (device globals; no allocation allowed) ----------
__device__ __half g_W1_h[Hh*Hh],            g_W1_l[Hh*Hh];
__device__ __half g_Wm_h[Pp*Hh],            g_Wm_l[Pp*Hh];
__device__ __half g_Wd_h[Pp*Hh],            g_Wd_l[Pp*Hh];
__device__ __half g_pool_h[(size_t)BT2*Hh];
__device__ __half g_pm_h[(size_t)BT2*KP];
__device__ __half g_pd_h[(size_t)Nn*KP],    g_pd_l[(size_t)Nn*KP];
__device__ float  g_part[(size_t)6*BT*3];   // logits partials per col-tile
__device__ __half g_sc[(size_t)BT2*Nn];     // scores, fp16
__device__ int    g_pred[BT];
__device__ int    g_rowinfo0[BT], g_rowinfo1[BT];
__device__ int    g_nvraw0[Bb],  g_nvraw1[Bb];
__device__ int    g_base0[Bb],   g_base1[Bb];
__device__ int    g_lsm_nv[2*Bb], g_lsm_base[2*Bb];
__device__ int    g_Rtot[4];                // [0]=Rpad [1]=R [2]=off0

// ---------------- helpers ----------------------------------------------------
__device__ __forceinline__ uint32_t smem_u32(const void* p){
    uint32_t a;
    asm("{ .reg .u64 t; cvta.to.shared.u64 t, %1; cvt.u32.u64 %0, t; }" : "=r"(a) : "l"(p));
    return a;
}
__device__ __forceinline__ void cp_async16(uint32_t dst, const void* src, bool ok){
    int sz = ok ? 16 : 0;
    asm volatile("cp.async.cg.shared.global [%0], [%1], 16, %2;" :: "r"(dst), "l"(src), "r"(sz));
}
__device__ __forceinline__ void cp_commit(){ asm volatile("cp.async.commit_group;" ::: "memory"); }
template<int N> __device__ __forceinline__ void cp_wait(){ asm volatile("cp.async.wait_group %0;" :: "n"(N) : "memory"); }

__device__ __forceinline__ void ldsm4(uint32_t* r, uint32_t addr){
    asm volatile("ldmatrix.sync.aligned.m8n8.x4.shared.b16 {%0,%1,%2,%3}, [%4];"
        : "=r"(r[0]), "=r"(r[1]), "=r"(r[2]), "=r"(r[3]) : "r"(addr));
}
__device__ __forceinline__ void mma16(float* d, const uint32_t* a, uint32_t b0, uint32_t b1){
    asm volatile(
        "mma.sync.aligned.m16n8k16.row.col.f32.f16.f16.f32 "
        "{%0,%1,%2,%3}, {%4,%5,%6,%7}, {%8,%9}, {%0,%1,%2,%3};"
        : "+f"(d[0]), "+f"(d[1]), "+f"(d[2]), "+f"(d[3])
        : "r"(a[0]), "r"(a[1]), "r"(a[2]), "r"(a[3]), "r"(b0), "r"(b1));
}
__device__ __forceinline__ void split16(float v, __half& h, __half& l){
    h = __float2half_rn(v);
    l = __float2half_rn(v - __half2float(h));
}

// ---------------- fp16 GEMM: C[M,N] = A[M,K] @ B[N,K]^T ----------------------
enum { EP_LOGITS = 0, EP_PAD = 1 };
#define ST_ALO 8192
#define ST_B   16384
#define ST_BLO 8192
#define STAGE  32768
#define SMEM_GEMM (3*STAGE)
#define SMEM_LOG  (3*STAGE + 6144 + 1536)
#define NTHR 256

template<int EPI, bool ROWMASK, int TERMS, bool CVT>
__global__ void __launch_bounds__(NTHR, 2) mma_gemm(
    const __half* __restrict__ Ah, const __half* __restrict__ Al,
    const float* __restrict__ Afp,
    const __half* __restrict__ Bh, const __half* __restrict__ Bl,
    float* __restrict__ C, __half* __restrict__ Ch, __half* __restrict__ Cl,
    int lda, int ldb, int ldc, int K, int Nreal, int NBreal,
    const float* __restrict__ bias, const int* __restrict__ rtot,
    const float* __restrict__ w2)
{
    extern __shared__ char smem[];
    const int m0 = blockIdx.y * 128, n0 = blockIdx.x * 128;
    const int tid = threadIdx.x;
    if (ROWMASK){
        if (m0 >= rtot[0]) return;
    }
    const uint32_t sb0 = smem_u32(smem);
    const int warp = tid >> 5, lane = tid & 31;
    const int wm = warp >> 2, wn = warp & 3;
    const int lr = lane >> 2, lc = lane & 3;

    float* psum = (float*)(smem + 3*STAGE);
    float* w2s  = (float*)(smem + 3*STAGE + 6144);
    if (EPI == EP_LOGITS && tid < 128){
        #pragma unroll
        for (int c = 0; c < 3; c++) w2s[c*128 + tid] = w2[c*Hh + n0 + tid];
    }

    float acc[4][4][4];
    #pragma unroll
    for (int i=0;i<4;i++)
        #pragma unroll
        for (int j=0;j<4;j++)
            #pragma unroll
            for (int q=0;q<4;q++) acc[i][j][q] = 0.f;

    const int arl = (lane & 7) + ((lane >> 3) & 1) * 8;
    const int acs = lane >> 4;
    const int nrl = (lane & 7) + (lane >> 4) * 8;
    const int bcs = (lane >> 3) & 1;
    uint32_t aoff[4], boff[2];
    #pragma unroll
    for (int mt = 0; mt < 4; mt++){
        int r = wm*64 + mt*16 + arl;
        int swz = acs ^ (r & 3) ^ ((r >> 2) & 1);
        if (CVT) aoff[mt] = (uint32_t)(((r >> 6) << 13) + ((r & 63) << 6) + (swz << 4));
        else     aoff[mt] = (uint32_t)((r << 6) + (swz << 4));
    }
    #pragma unroll
    for (int nb = 0; nb < 2; nb++){
        int r = wn*32 + nb*16 + nrl;
        boff[nb] = (uint32_t)ST_B + (uint32_t)((r << 6) + ((bcs ^ (r & 3) ^ ((r >> 2) & 1)) << 4));
    }
    const uint32_t ALO = CVT ? 4096u : (uint32_t)ST_ALO;

    auto load_tile = [&](int kt, int s){
        const int k0 = kt * 32;
        const uint32_t sbs = sb0 + (uint32_t)s * STAGE;
        if (CVT){
            #pragma unroll
            for (int j = 0; j < 8; j++){
                int idx = tid + j*NTHR;
                if (idx < 1024){
                    int row = idx >> 3, q = idx & 7;
                    uint32_t so = sbs + (uint32_t)(row*128 + q*16);
                    cp_async16(so, Afp + (size_t)(m0 + row)*lda + k0 + q*4, true);
                } else {
                    int b   = idx - 1024;
                    int pl  = b >> 9;
                    int rem = b & 511;
                    int row = rem >> 2, c = rem & 3;
                    int c2  = c ^ (row & 3) ^ ((row >> 2) & 1);
                    uint32_t so = sbs + (uint32_t)(ST_B + pl*ST_BLO + row*64 + c2*16);
                    bool ok = (n0 + row) < NBreal;
                    const __half* base = pl ? Bl : Bh;
                    const __half* src = ok ? (base + (size_t)(n0 + row)*ldb + k0 + c*8) : base;
                    cp_async16(so, src, ok);
                }
            }
        } else if (TERMS == 3){
            #pragma unroll
            for (int j = 0; j < 8; j++){
                int idx = tid + j*NTHR;
                if (idx < 1024){
                    int pl  = idx >> 9;
                    int rem = idx & 511;
                    int row = rem >> 2, c = rem & 3;
                    int c2  = c ^ (row & 3) ^ ((row >> 2) & 1);
                    uint32_t so = sbs + (uint32_t)(pl*ST_ALO + row*64 + c2*16);
                    const __half* src = (pl ? Al : Ah) + (size_t)(m0 + row)*lda + k0 + c*8;
                    cp_async16(so, src, true);
                } else {
                    int b   = idx - 1024;
                    int pl  = b >> 9;
                    int rem = b & 511;
                    int row = rem >> 2, c = rem & 3;
                    int c2  = c ^ (row & 3) ^ ((row >> 2) & 1);
                    uint32_t so = sbs + (uint32_t)(ST_B + pl*ST_BLO + row*64 + c2*16);
                    bool ok = (n0 + row) < NBreal;
                    const __half* base = pl ? Bl : Bh;
                    const __half* src = ok ? (base + (size_t)(n0 + row)*ldb + k0 + c*8) : base;
                    cp_async16(so, src, ok);
                }
            }
        } else {
            #pragma unroll
            for (int j = 0; j < 6; j++){
                int idx = tid + j*NTHR;
                if (idx < 512){
                    int row = idx >> 2, c = idx & 3;
                    int c2  = c ^ (row & 3) ^ ((row >> 2) & 1);
                    uint32_t so = sbs + (uint32_t)(row*64 + c2*16);
                    cp_async16(so, Ah + (size_t)(m0 + row)*lda + k0 + c*8, true);
                } else {
                    int b   = idx - 512;
                    int pl  = b >> 9;
                    int rem = b & 511;
                    int row = rem >> 2, c = rem & 3;
                    int c2  = c ^ (row & 3) ^ ((row >> 2) & 1);
                    uint32_t so = sbs + (uint32_t)(ST_B + pl*ST_BLO + row*64 + c2*16);
                    bool ok = (n0 + row) < NBreal;
                    const __half* base = pl ? Bl : Bh;
                    const __half* src = ok ? (base + (size_t)(n0 + row)*ldb + k0 + c*8) : base;
                    cp_async16(so, src, ok);
                }
            }
        }
        cp_commit();
    };

    const int nkt = K >> 5;
    load_tile(0, 0);
    if (nkt > 1) load_tile(1, 1);
    for (int kt = 0; kt < nkt; kt++){
        const int s = kt % 3;
        if (kt + 1 < nkt) cp_wait<1>(); else cp_wait<0>();
        __syncthreads();

        if (CVT){
            char* sp = smem + s*STAGE;
            #pragma unroll
            for (int rnd = 0; rnd < 2; rnd++){
                int r   = rnd*64 + (tid >> 2);
                int seg = tid & 3;
                const float4* fp = (const float4*)(sp + (r & 63)*128 + (r >> 6)*8192 + seg*32);
                float4 f0 = fp[0], f1 = fp[1];
                __syncthreads();
                float f[8] = {f0.x,f0.y,f0.z,f0.w,f1.x,f1.y,f1.z,f1.w};
                __half hv[8], lv[8];
                #pragma unroll
                for (int j = 0; j < 8; j++) split16(f[j], hv[j], lv[j]);
                int c2 = seg ^ (r & 3) ^ ((r >> 2) & 1);
                char* hp = sp + ((r >> 6) << 13) + ((r & 63) << 6) + (c2 << 4);
                *(uint4*)hp          = *(uint4*)hv;
                *(uint4*)(hp + 4096) = *(uint4*)lv;
                __syncthreads();
            }
        }

        if (kt + 2 < nkt) load_tile(kt + 2, (kt + 2) % 3);
        const uint32_t sbs = sb0 + (uint32_t)s * STAGE;

        #pragma unroll
        for (int ks = 0; ks < 2; ks++){
            const uint32_t kx = (uint32_t)(ks << 5);
            uint32_t bhf[2][4], blf[2][4];
            #pragma unroll
            for (int nb = 0; nb < 2; nb++){
                uint32_t t = (sbs + boff[nb]) ^ kx;
                ldsm4(bhf[nb], t);
                ldsm4(blf[nb], t + ST_BLO);
            }
            #pragma unroll
            for (int mt = 0; mt < 4; mt++){
                uint32_t ahf[4], alf[4];
                uint32_t t = (sbs + aoff[mt]) ^ kx;
                ldsm4(ahf, t);
                if (TERMS == 3) ldsm4(alf, t + ALO);
                #pragma unroll
                for (int nt = 0; nt < 4; nt++){
                    const int nb = nt >> 1, p = (nt & 1) * 2;
                    float* d = acc[mt][nt];
                    mma16(d, ahf, bhf[nb][p], bhf[nb][p+1]);
                    mma16(d, ahf, blf[nb][p], blf[nb][p+1]);
                    if (TERMS == 3)
                        mma16(d, alf, bhf[nb][p], bhf[nb][p+1]);
                }
            }
        }
        if (CVT) __syncthreads();
    }

    if (EPI == EP_LOGITS){
        float w2v[4][2][3];
        float bv[4][2];
        #pragma unroll
        for (int nt = 0; nt < 4; nt++){
            int colL = wn*32 + nt*8 + lc*2;
            #pragma unroll
            for (int j = 0; j < 2; j++){
                bv[nt][j] = bias[n0 + colL + j];
                #pragma unroll
                for (int c = 0; c < 3; c++) w2v[nt][j][c] = w2s[c*128 + colL + j];
            }
        }
        #pragma unroll
        for (int mt = 0; mt < 4; mt++){
            float pA[3] = {0.f,0.f,0.f}, pB[3] = {0.f,0.f,0.f};
            #pragma unroll
            for (int nt = 0; nt < 4; nt++){
                float* a = acc[mt][nt];
                float v0 = a[0] + bv[nt][0]; v0 = v0 > 0.f ? v0 : 0.f;
                float v1 = a[1] + bv[nt][1]; v1 = v1 > 0.f ? v1 : 0.f;
                float v2 = a[2] + bv[nt][0]; v2 = v2 > 0.f ? v2 : 0.f;
                float v3 = a[3] + bv[nt][1]; v3 = v3 > 0.f ? v3 : 0.f;
                #pragma unroll
                for (int c = 0; c < 3; c++){
                    pA[c] += v0*w2v[nt][0][c] + v1*w2v[nt][1][c];
                    pB[c] += v2*w2v[nt][0][c] + v3*w2v[nt][1][c];
                }
            }
            #pragma unroll
            for (int off = 1; off <= 2; off <<= 1){
                #pragma unroll
                for (int c = 0; c < 3; c++){
                    pA[c] += __shfl_xor_sync(0xffffffffu, pA[c], off);
                    pB[c] += __shfl_xor_sync(0xffffffffu, pB[c], off);
                }
            }
            if (lc == 0){
                int rA = wm*64 + mt*16 + lr;
                #pragma unroll
                for (int c = 0; c < 3; c++){
                    psum[(wn*128 + rA)*3 + c]     = pA[c];
                    psum[(wn*128 + rA + 8)*3 + c] = pB[c];
                }
            }
        }
        __syncthreads();
        for (int r = tid; r < 128; r += NTHR){
            #pragma unroll
            for (int c = 0; c < 3; c++){
                float g = psum[(0*128 + r)*3 + c];
                g += psum[(1*128 + r)*3 + c];
                g += psum[(2*128 + r)*3 + c];
                g += psum[(3*128 + r)*3 + c];
                C[((size_t)blockIdx.x*BT + (m0 + r))*3 + c] = g;
            }
        }
        return;
    }

    #pragma unroll
    for (int mt = 0; mt < 4; mt++){
        #pragma unroll
        for (int nt = 0; nt < 4; nt++){
            int row = m0 + wm*64 + mt*16 + lr;
            int col = n0 + wn*32 + nt*8 + lc*2;
            float* a = acc[mt][nt];
            if (col + 2 <= ldc){
                float v0 = (col   < Nreal) ? a[0] : 0.f;
                float v1 = (col+1 < Nreal) ? a[1] : 0.f;
                float v2 = (col   < Nreal) ? a[2] : 0.f;
                float v3 = (col+1 < Nreal) ? a[3] : 0.f;
                __half h0,l0,h1,l1,h2,l2,h3,l3;
                split16(v0,h0,l0); split16(v1,h1,l1);
                split16(v2,h2,l2); split16(v3,h3,l3);
                *(__half2*)&Ch[(size_t)row*ldc + col]     = __halves2half2(h0, h1);
                *(__half2*)&Ch[(size_t)(row+8)*ldc + col] = __halves2half2(h2, h3);
                if (Cl){
                    *(__half2*)&Cl[(size_t)row*ldc + col]     = __halves2half2(l0, l1);
                    *(__half2*)&Cl[(size_t)(row+8)*ldc + col] = __halves2half2(l2, l3);
                }
            }
        }
    }
}

// ---------------- fused weight split: W1 | Wm | Wd ------------------------------
__global__ void __launch_bounds__(256) fsplit_kernel(
    const float* __restrict__ W1, const float* __restrict__ Wm, const float* __restrict__ Wd,
    __half* __restrict__ w1h, __half* __restrict__ w1l,
    __half* __restrict__ wmh, __half* __restrict__ wml,
    __half* __restrict__ wdh, __half* __restrict__ wdl)
{
    const int n1 = Hh*Hh, n2 = n1 + Pp*Hh, n3 = n2 + Pp*Hh;
    int i = blockIdx.x*256 + threadIdx.x;
    const float* src; __half *dh, *dl; int off;
    if (i < n1){ src = W1; dh = w1h; dl = w1l; off = i; }
    else if (i < n2){ src = Wm;  dh = wmh;  dl = wml;  off = i - n1; }
    else if (i < n3){ src = Wd;  dh = wdh;  dl = wdl;  off = i - n2; }
    else return;
    __half hv, lv; split16(src[off], hv, lv); dh[off] = hv; dl[off] = lv;
}

// ---------------- final 3-class head ---------------------------------------------
__global__ void __launch_bounds__(256) logits2_kernel(
    const float* __restrict__ gpart, const float* __restrict__ b2,
    float* __restrict__ out0, int* __restrict__ pred)
{
    int row = blockIdx.x*256 + threadIdx.x;
    float s[3];
    #pragma unroll
    for (int c = 0; c < 3; c++) s[c] = b2[c];
    #pragma unroll
    for (int k = 0; k < 6; k++)
        #pragma unroll
        for (int c = 0; c < 3; c++)
            s[c] += gpart[((size_t)k*BT + row)*3 + c];
    float m = fmaxf(s[0], fmaxf(s[1], s[2]));
    float lse = m + logf(expf(s[0]-m)+expf(s[1]-m)+expf(s[2]-m));
    size_t o = (size_t)row*3;
    out0[o+0] = s[0] - lse; out0[o+1] = s[1] - lse; out0[o+2] = s[2] - lse;
    int idx = 0; float best = s[0];
    if (s[1] > best){ best = s[1]; idx = 1; }
    if (s[2] > best){ idx = 2; }
    pred[row] = idx;
}

// ---------------- BIO segment scan (single source) -------------------------------
__global__ void scan_kernel(const int* __restrict__ lsrc,
                            int* __restrict__ rowinfo, int* __restrict__ nvraw)
{
    __shared__ int pos[513];
    int b = blockIdx.x, lane = threadIdx.x;
    const int* lab = lsrc + b*Tt;
    int base = 0;
    int first1 = Tt;
    int any2 = 0;
    #pragma unroll 1
    for (int c = 0; c < Tt/32; c++){
        int l = lab[c*32 + lane];
        unsigned m1 = __ballot_sync(0xffffffffu, l == 1);
        unsigned m2 = __ballot_sync(0xffffffffu, l == 2);
        if (l == 1) pos[base + __popc(m1 & ((1u<<lane)-1))] = c*32 + lane;
        if (first1 == Tt){
            if (m1){
                int fl = __ffs(m1) - 1;
                first1 = c*32 + fl;
                any2 |= (m2 & ((1u<<fl)-1)) != 0;
            } else any2 |= (m2 != 0);
        }
        base += __popc(m1);
    }
    int m = base;
    int lead = any2;
    __syncwarp();
    if (lane == 0){
        pos[m] = Tt;
        if (lead) rowinfo[b*Tt] = (0<<16) | (m ? pos[0] : Tt);
        nvraw[b] = lead + m;
    }
    __syncwarp();
    for (int j = lane; j < m; j += 32){
        int s = pos[j], e = pos[j+1];
        rowinfo[b*Tt + lead + j] = (s<<16) | e;
    }
}

// ---------------- compaction, pass 0 ---------------------------------------------
__global__ void combineA_kernel(const int* __restrict__ nv0,
                                int* __restrict__ base0,
                                int* __restrict__ lsm_nv, int* __restrict__ lsm_base,
                                int* __restrict__ rtot)
{
    if (threadIdx.x || blockIdx.x) return;
    int off = 0, cnt = 0;
    for (int b = 0; b < Bb; b++){
        int nv = nv0[b];
        if (nv > 0){ base0[b] = off; lsm_base[cnt] = off; lsm_nv[cnt] = nv; cnt++; off += nv; }
        else base0[b] = -1;
    }
    for (int k = cnt; k < Bb; k++) lsm_nv[k] = 0;
    rtot[2] = off;
}

// ---------------- compaction, pass 1 + totals -------------------------------------
__global__ void combineB_kernel(const int* __restrict__ nv1,
                                int* __restrict__ base1,
                                int* __restrict__ lsm_nv, int* __restrict__ lsm_base,
                                int* __restrict__ rtot)
{
    if (threadIdx.x || blockIdx.x) return;
    int off = rtot[2], cnt = 0;
    for (int b = 0; b < Bb; b++){
        int nv = nv1[b];
        if (nv > 0){ base1[b] = off; lsm_base[Bb+cnt] = off; lsm_nv[Bb+cnt] = nv; cnt++; off += nv; }
        else base1[b] = -1;
    }
    for (int k = cnt; k < Bb; k++) lsm_nv[Bb+k] = 0;
    rtot[1] = off;
    rtot[0] = (off + 127) & ~127;
}

// ---------------- zero pooled pad rows --------------------------------------------
__global__ void __launch_bounds__(256) padzero_kernel(
    const int* __restrict__ rtot, __half* __restrict__ ph)
{
    int row = rtot[1] + blockIdx.x;
    if (row >= rtot[0]) return;
    size_t off = (size_t)row*Hh;
    __half z = __float2half(0.f);
    for (int i = threadIdx.x; i < Hh; i += 256) ph[off+i] = z;
}

// ---------------- segment means (single pass) -------------------------------------
__global__ void __launch_bounds__(256) pool_kernel(
    const int* __restrict__ lsrc, const float* __restrict__ hidden,
    const int* __restrict__ rowinfo, const int* __restrict__ nvarr,
    const int* __restrict__ basearr, __half* __restrict__ ph)
{
    int b = blockIdx.x;
    int d = basearr[b];
    if (d < 0) return;
    int nv = nvarr[b];
    __shared__ int labs[Tt];
    int tid = threadIdx.x;
    for (int i=tid;i<Tt;i+=256) labs[i] = lsrc[b*Tt+i];
    __syncthreads();
    int r0 = blockIdx.y * 32;
    int r1 = min(r0+32, nv);
    for (int r=r0; r<r1; r++){
        int info = rowinfo[b*Tt + r];
        int s = info >> 16, e = info & 0xffff;
        float a0=0.f,a1=0.f,a2=0.f;
        int cnt = 0;
        for (int t=s;t<e;t++){
            if (labs[t] != 0){
                cnt++;
                const float* hp = hidden + ((size_t)(b*Tt)+t)*Hh;
                a0 += hp[tid]; a1 += hp[tid+256]; a2 += hp[tid+512];
            }
        }
        float inv = 1.0f / (float)cnt;
        size_t off = ((size_t)(d + r))*Hh;
        ph[off+tid]     = __float2half_rn(a0*inv);
        ph[off+tid+256] = __float2half_rn(a1*inv);
        ph[off+tid+512] = __float2half_rn(a2*inv);
    }
}

// ---------------- row log-softmax over compacted fp16 sc --------------------------
__global__ void __launch_bounds__(256) lsm_kernel(
    const __half* __restrict__ sc, const int* __restrict__ lsm_nv,
    const int* __restrict__ lsm_base, float* __restrict__ out1, float* __restrict__ out2)
{
    int row = blockIdx.x*8 + (threadIdx.x >> 5);
    int p   = blockIdx.y;
    int lane = threadIdx.x & 31;
    int bb = row >> 9, t = row & 511;
    int nv = lsm_nv[p*Bb + bb];
    float* op = (p ? out2 : out1) + (size_t)row*Nn;
    if (t >= nv){
        const float CNEG = -7.6246189861593985f;
        float4 c4 = make_float4(CNEG,CNEG,CNEG,CNEG);
        for (int i=lane;i<Nn/4;i+=32) ((float4*)op)[i] = c4;
        return;
    }
    int srow = lsm_base[p*Bb + bb] + t;
    const uint2* ip = (const uint2*)(sc + (size_t)srow*Nn);
    float v[64];
    float m = -3.4e38f;
    #pragma unroll
    for (int i=0;i<16;i++){
        uint2 r = ip[lane + i*32];
        float2 f0 = __half22float2(*(__half2*)&r.x);
        float2 f1 = __half22float2(*(__half2*)&r.y);
        v[i*4+0]=f0.x; v[i*4+1]=f0.y; v[i*4+2]=f1.x; v[i*4+3]=f1.y;
        m = fmaxf(m, fmaxf(fmaxf(f0.x,f0.y), fmaxf(f1.x,f1.y)));
    }
    #pragma unroll
    for (int off=16;off;off>>=1) m = fmaxf(m, __shfl_xor_sync(0xffffffffu, m, off));
    float s = 0.f;
    #pragma unroll
    for (int i=0;i<64;i++) s += expf(v[i]-m);
    #pragma unroll
    for (int off=16;off;off>>=1) s += __shfl_xor_sync(0xffffffffu, s, off);
    float corr = m + logf(s);
    #pragma unroll
    for (int i=0;i<16;i++){
        float4 o = make_float4(v[i*4]-corr, v[i*4+1]-corr, v[i*4+2]-corr, v[i*4+3]-corr);
        ((float4*)op)[lane + i*32] = o;
    }
}

// ---------------- host -------------------------------------------------------------
extern "C" void kernel_launch(void* const* d_in, const int* in_sizes, int n_in,
                              void* d_out, int out_size)
{
    (void)in_sizes; (void)n_in; (void)out_size;
    const int*   labels = (const int*)  d_in[0];
    const float* hidden = (const float*)d_in[1];
    const float* ent    = (const float*)d_in[2];
    const float* W1     = (const float*)d_in[3];
    const float* b1     = (const float*)d_in[4];
    const float* W2     = (const float*)d_in[5];
    const float* b2     = (const float*)d_in[6];
    const float* Wm     = (const float*)d_in[7];
    const float* Wd     = (const float*)d_in[8];

    float* out0 = (float*)d_out;
    float* s1o  = out0 + (size_t)BT*3;
    float* s2o  = s1o  + (size_t)BT*Nn;

    __half *w1h,*w1l,*wmh,*wml,*wdh,*wdl;
    __half *poolh,*pmh,*pdh,*pdl,*sc;
    float *gpart;
    int *pred, *ri0, *ri1, *nv0, *nv1, *b0, *b1a, *lnv, *lbs, *rtot;
    cudaGetSymbolAddress((void**)&w1h,  g_W1_h);   cudaGetSymbolAddress((void**)&w1l,  g_W1_l);
    cudaGetSymbolAddress((void**)&wmh,  g_Wm_h);   cudaGetSymbolAddress((void**)&wml,  g_Wm_l);
    cudaGetSymbolAddress((void**)&wdh,  g_Wd_h);   cudaGetSymbolAddress((void**)&wdl,  g_Wd_l);
    cudaGetSymbolAddress((void**)&poolh,g_pool_h);
    cudaGetSymbolAddress((void**)&pmh,  g_pm_h);
    cudaGetSymbolAddress((void**)&pdh,  g_pd_h);   cudaGetSymbolAddress((void**)&pdl,  g_pd_l);
    cudaGetSymbolAddress((void**)&gpart,g_part);
    cudaGetSymbolAddress((void**)&sc,   g_sc);
    cudaGetSymbolAddress((void**)&pred, g_pred);
    cudaGetSymbolAddress((void**)&ri0,  g_rowinfo0);
    cudaGetSymbolAddress((void**)&ri1,  g_rowinfo1);
    cudaGetSymbolAddress((void**)&nv0,  g_nvraw0);
    cudaGetSymbolAddress((void**)&nv1,  g_nvraw1);
    cudaGetSymbolAddress((void**)&b0,   g_base0);
    cudaGetSymbolAddress((void**)&b1a,  g_base1);
    cudaGetSymbolAddress((void**)&lnv,  g_lsm_nv);
    cudaGetSymbolAddress((void**)&lbs,  g_lsm_base);
    cudaGetSymbolAddress((void**)&rtot, g_Rtot);

    cudaFuncSetAttribute((const void*)mma_gemm<EP_LOGITS,false,3,true>, cudaFuncAttributeMaxDynamicSharedMemorySize, SMEM_LOG);
    cudaFuncSetAttribute((const void*)mma_gemm<EP_PAD,false,2,true>,    cudaFuncAttributeMaxDynamicSharedMemorySize, SMEM_GEMM);
    cudaFuncSetAttribute((const void*)mma_gemm<EP_PAD,true,2,false>,    cudaFuncAttributeMaxDynamicSharedMemorySize, SMEM_GEMM);

    // one-time stream/event setup (no device memory allocation)
    static int inited = 0;
    static cudaStream_t sB = 0;
    static cudaEvent_t evStart, evF, evA, evB;
    if (!inited){
        inited = 1;
        if (cudaStreamCreateWithFlags(&sB, cudaStreamNonBlocking) != cudaSuccess) sB = 0;
        if (cudaEventCreateWithFlags(&evStart, cudaEventDisableTiming) != cudaSuccess) sB = 0;
        if (cudaEventCreateWithFlags(&evF, cudaEventDisableTiming) != cudaSuccess) sB = 0;
        if (cudaEventCreateWithFlags(&evA, cudaEventDisableTiming) != cudaSuccess) sB = 0;
        if (cudaEventCreateWithFlags(&evB, cudaEventDisableTiming) != cudaSuccess) sB = 0;
    }
    const bool fork = (sB != 0);
    cudaStream_t b = fork ? sB : 0;

    const int NSPLIT = Hh*Hh + 2*Pp*Hh;

    // fork stream B
    if (fork){ cudaEventRecord(evStart, 0); cudaStreamWaitEvent(sB, evStart, 0); }

    // stream B: scan0 -> combineA -> (evA) -> pool0 ; then after fsplit: pd -> (evB)
    scan_kernel<<<Bb, 32, 0, b>>>(labels, ri0, nv0);
    combineA_kernel<<<1, 1, 0, b>>>(nv0, b0, lnv, lbs, rtot);
    if (fork) cudaEventRecord(evA, sB);
    pool_kernel<<<dim3(Bb, 16), 256, 0, b>>>(labels, hidden, ri0, nv0, b0, poolh);

    // main: fsplit -> (evF) -> gemm1 -> logits2 -> scan1
    fsplit_kernel<<<(NSPLIT+255)/256, 256>>>(W1, Wm, Wd, w1h, w1l, wmh, wml, wdh, wdl);
    if (fork){ cudaEventRecord(evF, 0); cudaStreamWaitEvent(sB, evF, 0); }

    mma_gemm<EP_LOGITS,false,3,true><<<dim3(Hh/128, BT/128), NTHR, SMEM_LOG>>>(
        nullptr, nullptr, hidden, w1h, w1l, gpart, nullptr, nullptr,
        Hh, Hh, 3, Hh, Hh, Hh, b1, nullptr, W2);

    // stream B: pd = ent @ Wd^T (ent CVT'd in-kernel) — hidden under gemm1
    mma_gemm<EP_PAD,false,2,true><<<dim3(3, Nn/128), NTHR, SMEM_GEMM, b>>>(
        nullptr, nullptr, ent, wdh, wdl, nullptr, pdh, pdl,
        Hh, Hh, KP, Hh, Pp, Pp, nullptr, nullptr, nullptr);
    if (fork) cudaEventRecord(evB, sB);

    logits2_kernel<<<BT/256, 256>>>(gpart, b2, out0, pred);
    scan_kernel<<<Bb, 32>>>(pred, ri1, nv1);
    if (fork) cudaStreamWaitEvent(0, evA, 0);
    combineB_kernel<<<1, 1>>>(nv1, b1a, lnv, lbs, rtot);
    pool_kernel<<<dim3(Bb, 16), 256>>>(pred, hidden, ri1, nv1, b1a, poolh);
    padzero_kernel<<<128, 256>>>(rtot, poolh);

    // join stream B before pm/score (covers pool0 + pd)
    if (fork) cudaStreamWaitEvent(0, evB, 0);

    // pm = pooled @ Wm^T — 2-term, hi-plane output only
    mma_gemm<EP_PAD,true,2,false><<<dim3(3, BT2/128), NTHR, SMEM_GEMM>>>(
        poolh, nullptr, nullptr, wmh, wml, nullptr, pmh, nullptr,
        Hh, Hh, KP, Hh, Pp, Pp, nullptr, rtot, nullptr);

    // sc = pm @ pd^T — 2-term, fp16 output
    mma_gemm<EP_PAD,true,2,false><<<dim3(Nn/128, BT2/128), NTHR, SMEM_GEMM>>>(
        pmh, nullptr, nullptr, pdh, pdl, nullptr, sc, nullptr,
        KP, KP, Nn, KP, Nn, Nn, nullptr, rtot, nullptr);

    // log-softmax scatter to both outputs
    lsm_kernel<<<dim3(BT/8, 2), 256>>>(sc, lnv, lbs, s1o, s2o);
}